// round 2
// baseline (speedup 1.0000x reference)
#include <cuda_runtime.h>
#include <math.h>

#define B_ 32
#define S_ 2048
#define E_ 1024
#define D_ 1024
#define K_ E_
#define M_ (S_ * B_)   // 65536 rows of the big GEMM

// Scratch (no allocations allowed in kernel_launch)
__device__ float g_scores[B_ * S_];   // pre-softmax scores [B,S]
__device__ float g_dec[B_ * D_];      // dec_proj [B,D]

// ---------------------------------------------------------------------------
// 0. init: zero scores scratch and the context region of d_out
// ---------------------------------------------------------------------------
__global__ void init_kernel(float* __restrict__ out) {
    int i = blockIdx.x * blockDim.x + threadIdx.x;
    if (i < B_ * S_) g_scores[i] = 0.f;
    if (i < B_ * E_) out[i] = 0.f;
}

// ---------------------------------------------------------------------------
// 1. dec_proj[b*D+d] = sum_k hidden[b,k] * Wd[d,k]   (warp per output)
// ---------------------------------------------------------------------------
__global__ __launch_bounds__(256)
void dec_proj_kernel(const float* __restrict__ hidden, const float* __restrict__ Wd) {
    int warp = (blockIdx.x * blockDim.x + threadIdx.x) >> 5;
    int lane = threadIdx.x & 31;
    if (warp >= B_ * D_) return;
    int b = warp >> 10;        // / D_
    int d = warp & (D_ - 1);
    const float4* h4 = (const float4*)(hidden + (size_t)b * D_);
    const float4* w4 = (const float4*)(Wd + (size_t)d * D_);
    float s = 0.f;
#pragma unroll
    for (int k = lane; k < D_ / 4; k += 32) {
        float4 a = h4[k], w = w4[k];
        s += a.x * w.x + a.y * w.y + a.z * w.z + a.w * w.w;
    }
#pragma unroll
    for (int o = 16; o; o >>= 1) s += __shfl_down_sync(0xffffffffu, s, o);
    if (!lane) g_dec[warp] = s;
}

// ---------------------------------------------------------------------------
// 2. Fused scores GEMM:
//    C[m,n] = sum_k enc_flat[m,k] * We[n,k]     (m = s*B + b)
//    epilogue: t = tanh(C + dec_proj[b,n]); scores[b,s] += t * v[n]
//    128x128 block tile, 8x8 per thread, BK=16, fp32.
// ---------------------------------------------------------------------------
__global__ __launch_bounds__(256)
void score_gemm_kernel(const float* __restrict__ A,   // [M_, K_] enc flattened
                       const float* __restrict__ We,  // [D_, K_]
                       const float* __restrict__ v) { // [D_]
    __shared__ float As[16][128];
    __shared__ float Bs[16][128];
    __shared__ float red[128][17];

    const int tid = threadIdx.x;
    const int ty = tid >> 4, tx = tid & 15;
    const size_t m_base = (size_t)blockIdx.x * 128;
    const int n_base = blockIdx.y * 128;

    const int lr = tid >> 2;          // 0..63
    const int lc = (tid & 3) << 2;    // 0,4,8,12

    float acc[8][8];
#pragma unroll
    for (int i = 0; i < 8; i++)
#pragma unroll
        for (int j = 0; j < 8; j++) acc[i][j] = 0.f;

    const float* Ap = A + (m_base + lr) * (size_t)K_ + lc;
    const float* Bp = We + (size_t)(n_base + lr) * K_ + lc;

    for (int k0 = 0; k0 < K_; k0 += 16) {
        float4 a0 = *(const float4*)(Ap + k0);
        float4 a1 = *(const float4*)(Ap + (size_t)64 * K_ + k0);
        float4 b0 = *(const float4*)(Bp + k0);
        float4 b1 = *(const float4*)(Bp + (size_t)64 * K_ + k0);

        As[lc + 0][lr] = a0.x; As[lc + 1][lr] = a0.y;
        As[lc + 2][lr] = a0.z; As[lc + 3][lr] = a0.w;
        As[lc + 0][lr + 64] = a1.x; As[lc + 1][lr + 64] = a1.y;
        As[lc + 2][lr + 64] = a1.z; As[lc + 3][lr + 64] = a1.w;
        Bs[lc + 0][lr] = b0.x; Bs[lc + 1][lr] = b0.y;
        Bs[lc + 2][lr] = b0.z; Bs[lc + 3][lr] = b0.w;
        Bs[lc + 0][lr + 64] = b1.x; Bs[lc + 1][lr + 64] = b1.y;
        Bs[lc + 2][lr + 64] = b1.z; Bs[lc + 3][lr + 64] = b1.w;
        __syncthreads();

#pragma unroll
        for (int kk = 0; kk < 16; kk++) {
            float ra[8], rb[8];
#pragma unroll
            for (int i = 0; i < 8; i++) ra[i] = As[kk][ty * 8 + i];
#pragma unroll
            for (int j = 0; j < 8; j++) rb[j] = Bs[kk][tx * 8 + j];
#pragma unroll
            for (int i = 0; i < 8; i++)
#pragma unroll
                for (int j = 0; j < 8; j++) acc[i][j] += ra[i] * rb[j];
        }
        __syncthreads();
    }

    // Epilogue: tanh + dot with v, reduce across the N tile.
#pragma unroll
    for (int i = 0; i < 8; i++) {
        size_t m = m_base + ty * 8 + i;
        int b = (int)(m & (B_ - 1));
        float rs = 0.f;
#pragma unroll
        for (int j = 0; j < 8; j++) {
            int n = n_base + tx * 8 + j;
            float t = tanhf(acc[i][j] + g_dec[b * D_ + n]);
            rs += t * v[n];
        }
        red[ty * 8 + i][tx] = rs;
    }
    __syncthreads();

    int row = tid >> 1, half = tid & 1;
    float s = 0.f;
#pragma unroll
    for (int j = 0; j < 8; j++) s += red[row][half * 8 + j];
    s += __shfl_down_sync(0xffffffffu, s, 1);
    if (!half) {
        size_t m = m_base + row;
        atomicAdd(&g_scores[(m & (B_ - 1)) * S_ + (m >> 5)], s);
    }
}

// ---------------------------------------------------------------------------
// 3. Softmax over S per batch row; writes attention_weights into d_out
// ---------------------------------------------------------------------------
__global__ __launch_bounds__(256)
void softmax_kernel(float* __restrict__ wout) {
    int b = blockIdx.x;
    int tid = threadIdx.x;
    __shared__ float sm[256];

    float vals[8];
    float mx = -1e30f;
#pragma unroll
    for (int i = 0; i < 8; i++) {
        vals[i] = g_scores[b * S_ + tid + i * 256];
        mx = fmaxf(mx, vals[i]);
    }
    sm[tid] = mx; __syncthreads();
    for (int o = 128; o; o >>= 1) {
        if (tid < o) sm[tid] = fmaxf(sm[tid], sm[tid + o]);
        __syncthreads();
    }
    mx = sm[0]; __syncthreads();

    float sum = 0.f;
#pragma unroll
    for (int i = 0; i < 8; i++) { vals[i] = expf(vals[i] - mx); sum += vals[i]; }
    sm[tid] = sum; __syncthreads();
    for (int o = 128; o; o >>= 1) {
        if (tid < o) sm[tid] += sm[tid + o];
        __syncthreads();
    }
    float inv = 1.f / sm[0];
#pragma unroll
    for (int i = 0; i < 8; i++) wout[b * S_ + tid + i * 256] = vals[i] * inv;
}

// ---------------------------------------------------------------------------
// 4. context[b,e] = sum_s w[b,s] * enc[s,b,e]  (split over S, atomic combine)
// ---------------------------------------------------------------------------
#define CSPLIT 8
__global__ __launch_bounds__(256)
void context_kernel(const float* __restrict__ enc, const float* __restrict__ w,
                    float* __restrict__ ctx) {
    int e = blockIdx.x * 256 + threadIdx.x;
    int b = blockIdx.y;
    int s0 = blockIdx.z * (S_ / CSPLIT);
    const float* base = enc + (size_t)b * E_ + e;
    float acc0 = 0.f, acc1 = 0.f, acc2 = 0.f, acc3 = 0.f;
#pragma unroll 2
    for (int s = s0; s < s0 + S_ / CSPLIT; s += 4) {
        acc0 += w[b * S_ + s + 0] * base[(size_t)(s + 0) * (B_ * E_)];
        acc1 += w[b * S_ + s + 1] * base[(size_t)(s + 1) * (B_ * E_)];
        acc2 += w[b * S_ + s + 2] * base[(size_t)(s + 2) * (B_ * E_)];
        acc3 += w[b * S_ + s + 3] * base[(size_t)(s + 3) * (B_ * E_)];
    }
    atomicAdd(&ctx[b * E_ + e], (acc0 + acc1) + (acc2 + acc3));
}

// ---------------------------------------------------------------------------
extern "C" void kernel_launch(void* const* d_in, const int* in_sizes, int n_in,
                              void* d_out, int out_size) {
    const float* hidden = (const float*)d_in[0];  // [B,D]
    const float* enc    = (const float*)d_in[1];  // [S,B,E]
    const float* We     = (const float*)d_in[2];  // [D,E]
    const float* Wd     = (const float*)d_in[3];  // [D,D]
    const float* v      = (const float*)d_in[4];  // [D]
    float* out = (float*)d_out;                   // [B*E context | B*S weights]
    float* wout = out + B_ * E_;

    init_kernel<<<(B_ * S_ + 255) / 256, 256>>>(out);
    dec_proj_kernel<<<(B_ * D_ * 32 + 255) / 256, 256>>>(hidden, Wd);
    score_gemm_kernel<<<dim3(M_ / 128, D_ / 128), 256>>>(enc, We, v);
    softmax_kernel<<<B_, 256>>>(wout);
    context_kernel<<<dim3(E_ / 256, B_, CSPLIT), 256>>>(enc, wout, out);
}

// round 4
// speedup vs baseline: 1.8084x; 1.8084x over previous
#include <cuda_runtime.h>
#include <cuda_bf16.h>
#include <math.h>
#include <stdint.h>

#define B_ 32
#define S_ 2048
#define E_ 1024
#define D_ 1024
#define K_ 1024
#define M_ (S_ * B_)   // 65536

// GEMM tiling
#define CTAM 128
#define CTAN 128
#define CKS 32                 // K per chunk
#define NCHUNK (K_ / CKS)      // 32
#define NT (D_ / CTAN)         // 8
#define MT (M_ / CTAM)         // 512

// SMEM: 4 tiles of 128 rows x 64B (32 bf16) = 8KB each
#define OFF_AHI 0
#define OFF_ALO 8192
#define OFF_BHI 16384
#define OFF_BLO 24576
#define SMEM_BYTES 32768

__device__ float g_scores[B_ * S_];
__device__ float g_dec[B_ * D_];

// ---------------------------------------------------------------------------
__device__ __forceinline__ uint32_t smem_u32(const void* p) {
    uint32_t a;
    asm("{ .reg .u64 t; cvta.to.shared.u64 t, %1; cvt.u32.u64 %0, t; }" : "=r"(a) : "l"(p));
    return a;
}

__device__ __forceinline__ uint32_t pack2(float a, float b) {
    uint32_t r;  // low half = a, high half = b
    asm("cvt.rn.bf16x2.f32 %0, %1, %2;" : "=r"(r) : "f"(b), "f"(a));
    return r;
}

__device__ __forceinline__ uint32_t pack_hi(float a, float b, float& ra, float& rb) {
    uint32_t r = pack2(a, b);
    __nv_bfloat162 h = *(__nv_bfloat162*)&r;
    ra = a - __bfloat162float(h.x);
    rb = b - __bfloat162float(h.y);
    return r;
}

// 16B-group swizzled offset within a 128x64B tile
__device__ __forceinline__ uint32_t sw_off(uint32_t row, uint32_t g) {
    return (row << 6) | (((g ^ row) & 3u) << 4);
}

__device__ __forceinline__ void ldsm4(uint32_t* r, uint32_t addr) {
    asm volatile("ldmatrix.sync.aligned.m8n8.x4.shared.b16 {%0,%1,%2,%3}, [%4];"
                 : "=r"(r[0]), "=r"(r[1]), "=r"(r[2]), "=r"(r[3]) : "r"(addr));
}

__device__ __forceinline__ void mma_bf16(float* d, const uint32_t* a, const uint32_t* b) {
    asm volatile(
        "mma.sync.aligned.m16n8k16.row.col.f32.bf16.bf16.f32 "
        "{%0,%1,%2,%3}, {%4,%5,%6,%7}, {%8,%9}, {%0,%1,%2,%3};"
        : "+f"(d[0]), "+f"(d[1]), "+f"(d[2]), "+f"(d[3])
        : "r"(a[0]), "r"(a[1]), "r"(a[2]), "r"(a[3]), "r"(b[0]), "r"(b[1]));
}

// tanh via rational approx (FMA-only, no MUFU in the hot path)
__device__ __forceinline__ float fast_tanh(float x) {
    float cx = fminf(fmaxf(x, -7.90531110763549805f), 7.90531110763549805f);
    float x2 = cx * cx;
    float p = fmaf(x2, -2.76076847742355e-16f, 2.00018790482477e-13f);
    p = fmaf(p, x2, -8.60467152213735e-11f);
    p = fmaf(p, x2, 5.12229709037114e-08f);
    p = fmaf(p, x2, 1.48572235717979e-05f);
    p = fmaf(p, x2, 6.37261928875436e-04f);
    p = fmaf(p, x2, 4.89352455891786e-03f);
    p = p * cx;
    float q = fmaf(x2, 1.19825839466702e-06f, 1.18534705686654e-04f);
    q = fmaf(q, x2, 2.26843463243900e-03f);
    q = fmaf(q, x2, 4.89352518554385e-03f);
    float r = __uint_as_float(0x7EF127EAu - __float_as_uint(q));
    r = r * (2.0f - q * r);
    r = r * (2.0f - q * r);
    r = r * (2.0f - q * r);
    return p * r;
}

// ---------------------------------------------------------------------------
// 0. init
// ---------------------------------------------------------------------------
__global__ void init_kernel(float* __restrict__ out) {
    int i = blockIdx.x * blockDim.x + threadIdx.x;
    if (i < B_ * S_) g_scores[i] = 0.f;
    if (i < B_ * E_) out[i] = 0.f;
}

// ---------------------------------------------------------------------------
// 1. dec_proj[b*D+d] = sum_k hidden[b,k] * Wd[d,k]
// ---------------------------------------------------------------------------
__global__ __launch_bounds__(256)
void dec_proj_kernel(const float* __restrict__ hidden, const float* __restrict__ Wd) {
    int warp = (blockIdx.x * blockDim.x + threadIdx.x) >> 5;
    int lane = threadIdx.x & 31;
    if (warp >= B_ * D_) return;
    int b = warp >> 10;
    int d = warp & (D_ - 1);
    const float4* h4 = (const float4*)(hidden + (size_t)b * D_);
    const float4* w4 = (const float4*)(Wd + (size_t)d * D_);
    float s = 0.f;
#pragma unroll
    for (int k = lane; k < D_ / 4; k += 32) {
        float4 a = h4[k], w = w4[k];
        s += a.x * w.x + a.y * w.y + a.z * w.z + a.w * w.w;
    }
#pragma unroll
    for (int o = 16; o; o >>= 1) s += __shfl_down_sync(0xffffffffu, s, o);
    if (!lane) g_dec[warp] = s;
}

// ---------------------------------------------------------------------------
// 2. Fused scores GEMM on HMMA (mma.sync bf16, 3-pass split for fp32 accuracy)
//    C[m,n] = sum_k enc[m,k]*We[n,k]; epi: scores[b,s] += tanh(C+dec)·v
// ---------------------------------------------------------------------------
__global__ __launch_bounds__(256)
void score_mma_kernel(const float* __restrict__ A,    // [M_,K_] enc flattened
                      const float* __restrict__ We,   // [D_,K_]
                      const float* __restrict__ v) {
    __shared__ __align__(1024) char smem[SMEM_BYTES];
    const uint32_t sb = smem_u32(smem);

    const int tid = threadIdx.x;
    const int wid = tid >> 5;
    const int lane = tid & 31;
    const int wm = wid >> 1;          // 0..3
    const int wn = wid & 1;           // 0..1
    const int n_base = blockIdx.x * CTAN;
    const size_t m_base = (size_t)blockIdx.y * CTAM;

    // per-thread load task: row r (0..127), half h (0..1) -> 16 fp32
    const int lr = tid >> 1;
    const int lh = tid & 1;
    const float* Ag = A + (m_base + lr) * (size_t)K_ + lh * 16;
    const float* Bg = We + (size_t)(n_base + lr) * K_ + lh * 16;

    float acc[2][8][4];
#pragma unroll
    for (int mt = 0; mt < 2; mt++)
#pragma unroll
        for (int j = 0; j < 8; j++)
#pragma unroll
            for (int cc = 0; cc < 4; cc++) acc[mt][j][cc] = 0.f;

    float4 fa[4], fb[4];

    // helper lambdas via macros: load chunk c into regs
#define LOAD_CHUNK(c)                                                         \
    {                                                                         \
        const float4* ap = (const float4*)(Ag + (c) * CKS);                   \
        const float4* bp = (const float4*)(Bg + (c) * CKS);                   \
        fa[0] = ap[0]; fa[1] = ap[1]; fa[2] = ap[2]; fa[3] = ap[3];           \
        fb[0] = bp[0]; fb[1] = bp[1]; fb[2] = bp[2]; fb[3] = bp[3];           \
    }

#define CVT_STORE()                                                           \
    {                                                                         \
        uint32_t h[8], l[8];                                                  \
        float r0, r1, r2, r3;                                                 \
        _Pragma("unroll")                                                     \
        for (int i = 0; i < 4; i++) {                                         \
            h[2*i]   = pack_hi(fa[i].x, fa[i].y, r0, r1);                     \
            h[2*i+1] = pack_hi(fa[i].z, fa[i].w, r2, r3);                     \
            l[2*i]   = pack2(r0, r1);                                         \
            l[2*i+1] = pack2(r2, r3);                                         \
        }                                                                     \
        uint32_t o0 = sw_off(lr, lh * 2), o1 = sw_off(lr, lh * 2 + 1);        \
        *(uint4*)(smem + OFF_AHI + o0) = make_uint4(h[0], h[1], h[2], h[3]);  \
        *(uint4*)(smem + OFF_AHI + o1) = make_uint4(h[4], h[5], h[6], h[7]);  \
        *(uint4*)(smem + OFF_ALO + o0) = make_uint4(l[0], l[1], l[2], l[3]);  \
        *(uint4*)(smem + OFF_ALO + o1) = make_uint4(l[4], l[5], l[6], l[7]);  \
        _Pragma("unroll")                                                     \
        for (int i = 0; i < 4; i++) {                                         \
            h[2*i]   = pack_hi(fb[i].x, fb[i].y, r0, r1);                     \
            h[2*i+1] = pack_hi(fb[i].z, fb[i].w, r2, r3);                     \
            l[2*i]   = pack2(r0, r1);                                         \
            l[2*i+1] = pack2(r2, r3);                                         \
        }                                                                     \
        *(uint4*)(smem + OFF_BHI + o0) = make_uint4(h[0], h[1], h[2], h[3]);  \
        *(uint4*)(smem + OFF_BHI + o1) = make_uint4(h[4], h[5], h[6], h[7]);  \
        *(uint4*)(smem + OFF_BLO + o0) = make_uint4(l[0], l[1], l[2], l[3]);  \
        *(uint4*)(smem + OFF_BLO + o1) = make_uint4(l[4], l[5], l[6], l[7]);  \
    }

    LOAD_CHUNK(0);
    CVT_STORE();
    __syncthreads();

    // ldmatrix base addresses (per-lane row/group components)
    const uint32_t a_row = wm * 32 + (lane & 15);
    const uint32_t a_kg = (uint32_t)(lane >> 4);
    const uint32_t b_row_lo = wn * 64 + (lane & 7) + ((lane & 16) ? 8 : 0);
    const uint32_t b_kg = (uint32_t)((lane >> 3) & 1);

    for (int c = 0; c < NCHUNK; c++) {
        if (c + 1 < NCHUNK) LOAD_CHUNK(c + 1);

#pragma unroll
        for (int ks = 0; ks < 2; ks++) {
            uint32_t ah[2][4], al[2][4];
#pragma unroll
            for (int mt = 0; mt < 2; mt++) {
                uint32_t off = sw_off(a_row + mt * 16, a_kg + 2 * ks);
                ldsm4(ah[mt], sb + OFF_AHI + off);
                ldsm4(al[mt], sb + OFF_ALO + off);
            }
#pragma unroll
            for (int half = 0; half < 2; half++) {   // n-tiles 4 at a time
                uint32_t bh[4][2], bl[4][2];
#pragma unroll
                for (int j2 = 0; j2 < 2; j2++) {
                    uint32_t off = sw_off(b_row_lo + (half * 2 + j2) * 16, b_kg + 2 * ks);
                    uint32_t t[4];
                    ldsm4(t, sb + OFF_BHI + off);
                    bh[j2 * 2][0] = t[0]; bh[j2 * 2][1] = t[1];
                    bh[j2 * 2 + 1][0] = t[2]; bh[j2 * 2 + 1][1] = t[3];
                    ldsm4(t, sb + OFF_BLO + off);
                    bl[j2 * 2][0] = t[0]; bl[j2 * 2][1] = t[1];
                    bl[j2 * 2 + 1][0] = t[2]; bl[j2 * 2 + 1][1] = t[3];
                }
#pragma unroll
                for (int mt = 0; mt < 2; mt++)
#pragma unroll
                    for (int j = 0; j < 4; j++) {
                        float* d = acc[mt][half * 4 + j];
                        mma_bf16(d, ah[mt], bh[j]);   // hi*hi
                        mma_bf16(d, ah[mt], bl[j]);   // hi*lo
                        mma_bf16(d, al[mt], bh[j]);   // lo*hi
                    }
            }
        }
        __syncthreads();
        if (c + 1 < NCHUNK) {
            CVT_STORE();
        }
        __syncthreads();
    }

    // ---- epilogue: stage dec tile + v into smem (reuse), tanh + v-dot ----
    float* sdec = (float*)smem;            // [32][128]
    float* sv = (float*)(smem + 16384);    // [128]
    for (int i = tid; i < B_ * CTAN; i += 256) {
        int b = i >> 7, n = i & (CTAN - 1);
        sdec[b * CTAN + n] = g_dec[b * D_ + n_base + n];
    }
    if (tid < CTAN) sv[tid] = v[n_base + tid];
    __syncthreads();

#pragma unroll
    for (int mt = 0; mt < 2; mt++) {
        int rowA = wm * 32 + mt * 16 + (lane >> 2);   // and rowA+8
        int b0 = rowA & 31, b1 = (rowA + 8) & 31;
        float s0 = 0.f, s1 = 0.f;
#pragma unroll
        for (int j = 0; j < 8; j++) {
            int nc = wn * 64 + j * 8 + (lane & 3) * 2;
            float v0 = sv[nc], v1 = sv[nc + 1];
            s0 = fmaf(fast_tanh(acc[mt][j][0] + sdec[b0 * CTAN + nc]), v0, s0);
            s0 = fmaf(fast_tanh(acc[mt][j][1] + sdec[b0 * CTAN + nc + 1]), v1, s0);
            s1 = fmaf(fast_tanh(acc[mt][j][2] + sdec[b1 * CTAN + nc]), v0, s1);
            s1 = fmaf(fast_tanh(acc[mt][j][3] + sdec[b1 * CTAN + nc + 1]), v1, s1);
        }
        s0 += __shfl_xor_sync(0xffffffffu, s0, 1);
        s0 += __shfl_xor_sync(0xffffffffu, s0, 2);
        s1 += __shfl_xor_sync(0xffffffffu, s1, 1);
        s1 += __shfl_xor_sync(0xffffffffu, s1, 2);
        if ((lane & 3) == 0) {
            size_t m0 = m_base + rowA;
            size_t m1 = m0 + 8;
            atomicAdd(&g_scores[(m0 & 31) * S_ + (m0 >> 5)], s0);
            atomicAdd(&g_scores[(m1 & 31) * S_ + (m1 >> 5)], s1);
        }
    }
}

// ---------------------------------------------------------------------------
// 3. softmax over S per batch
// ---------------------------------------------------------------------------
__global__ __launch_bounds__(256)
void softmax_kernel(float* __restrict__ wout) {
    int b = blockIdx.x;
    int tid = threadIdx.x;
    __shared__ float sm[256];

    float vals[8];
    float mx = -1e30f;
#pragma unroll
    for (int i = 0; i < 8; i++) {
        vals[i] = g_scores[b * S_ + tid + i * 256];
        mx = fmaxf(mx, vals[i]);
    }
    sm[tid] = mx; __syncthreads();
    for (int o = 128; o; o >>= 1) {
        if (tid < o) sm[tid] = fmaxf(sm[tid], sm[tid + o]);
        __syncthreads();
    }
    mx = sm[0]; __syncthreads();

    float sum = 0.f;
#pragma unroll
    for (int i = 0; i < 8; i++) { vals[i] = expf(vals[i] - mx); sum += vals[i]; }
    sm[tid] = sum; __syncthreads();
    for (int o = 128; o; o >>= 1) {
        if (tid < o) sm[tid] += sm[tid + o];
        __syncthreads();
    }
    float inv = 1.f / sm[0];
#pragma unroll
    for (int i = 0; i < 8; i++) wout[b * S_ + tid + i * 256] = vals[i] * inv;
}

// ---------------------------------------------------------------------------
// 4. context[b,e] = sum_s w[b,s] * enc[s,b,e]
// ---------------------------------------------------------------------------
#define CSPLIT 8
__global__ __launch_bounds__(256)
void context_kernel(const float* __restrict__ enc, const float* __restrict__ w,
                    float* __restrict__ ctx) {
    int e = blockIdx.x * 256 + threadIdx.x;
    int b = blockIdx.y;
    int s0 = blockIdx.z * (S_ / CSPLIT);
    const float* base = enc + (size_t)b * E_ + e;
    float acc0 = 0.f, acc1 = 0.f, acc2 = 0.f, acc3 = 0.f;
#pragma unroll 2
    for (int s = s0; s < s0 + S_ / CSPLIT; s += 4) {
        acc0 += w[b * S_ + s + 0] * base[(size_t)(s + 0) * (B_ * E_)];
        acc1 += w[b * S_ + s + 1] * base[(size_t)(s + 1) * (B_ * E_)];
        acc2 += w[b * S_ + s + 2] * base[(size_t)(s + 2) * (B_ * E_)];
        acc3 += w[b * S_ + s + 3] * base[(size_t)(s + 3) * (B_ * E_)];
    }
    atomicAdd(&ctx[b * E_ + e], (acc0 + acc1) + (acc2 + acc3));
}

// ---------------------------------------------------------------------------
extern "C" void kernel_launch(void* const* d_in, const int* in_sizes, int n_in,
                              void* d_out, int out_size) {
    const float* hidden = (const float*)d_in[0];  // [B,D]
    const float* enc    = (const float*)d_in[1];  // [S,B,E]
    const float* We     = (const float*)d_in[2];  // [D,E]
    const float* Wd     = (const float*)d_in[3];  // [D,D]
    const float* v      = (const float*)d_in[4];  // [D]
    float* out = (float*)d_out;                   // [B*E context | B*S weights]
    float* wout = out + B_ * E_;

    init_kernel<<<(B_ * S_ + 255) / 256, 256>>>(out);
    dec_proj_kernel<<<(B_ * D_ * 32 + 255) / 256, 256>>>(hidden, Wd);
    score_mma_kernel<<<dim3(NT, MT), 256>>>(enc, We, v);
    softmax_kernel<<<B_, 256>>>(wout);
    context_kernel<<<dim3(E_ / 256, B_, CSPLIT), 256>>>(enc, wout, out);
}

// round 5
// speedup vs baseline: 2.0247x; 1.1196x over previous
#include <cuda_runtime.h>
#include <cuda_bf16.h>
#include <math.h>
#include <stdint.h>

#define B_ 32
#define S_ 2048
#define E_ 1024
#define D_ 1024
#define K_ 1024
#define M_ (S_ * B_)   // 65536

// GEMM tiling
#define CTAM 128
#define CTAN 128
#define CKS 32                 // K per chunk
#define NCHUNK (K_ / CKS)      // 32
#define NT (D_ / CTAN)         // 8
#define MT (M_ / CTAM)         // 512

// SMEM per stage: 4 tiles of 128 rows x 64B = 8KB each
#define OFF_AHI 0
#define OFF_ALO 8192
#define OFF_BHI 16384
#define OFF_BLO 24576
#define STAGE_BYTES 32768
#define SMEM_BYTES (2 * STAGE_BYTES)   // 64KB dynamic

__device__ float g_scores[B_ * S_];
__device__ float g_dec[B_ * D_];
__device__ __nv_bfloat16 g_ahi[(size_t)M_ * K_];
__device__ __nv_bfloat16 g_alo[(size_t)M_ * K_];
__device__ __nv_bfloat16 g_bhi[(size_t)D_ * K_];
__device__ __nv_bfloat16 g_blo[(size_t)D_ * K_];

// ---------------------------------------------------------------------------
__device__ __forceinline__ uint32_t smem_u32(const void* p) {
    uint32_t a;
    asm("{ .reg .u64 t; cvta.to.shared.u64 t, %1; cvt.u32.u64 %0, t; }" : "=r"(a) : "l"(p));
    return a;
}

__device__ __forceinline__ uint32_t pack2(float a, float b) {
    uint32_t r;  // low half = a, high half = b
    asm("cvt.rn.bf16x2.f32 %0, %1, %2;" : "=r"(r) : "f"(b), "f"(a));
    return r;
}

__device__ __forceinline__ uint32_t pack_hi(float a, float b, float& ra, float& rb) {
    uint32_t r = pack2(a, b);
    __nv_bfloat162 h = *(__nv_bfloat162*)&r;
    ra = a - __bfloat162float(h.x);
    rb = b - __bfloat162float(h.y);
    return r;
}

// 16B-group swizzled offset within a 128x64B tile
__device__ __forceinline__ uint32_t sw_off(uint32_t row, uint32_t g) {
    return (row << 6) | (((g ^ row) & 3u) << 4);
}

__device__ __forceinline__ void ldsm4(uint32_t* r, uint32_t addr) {
    asm volatile("ldmatrix.sync.aligned.m8n8.x4.shared.b16 {%0,%1,%2,%3}, [%4];"
                 : "=r"(r[0]), "=r"(r[1]), "=r"(r[2]), "=r"(r[3]) : "r"(addr));
}

__device__ __forceinline__ void mma_bf16(float* d, const uint32_t* a, const uint32_t* b) {
    asm volatile(
        "mma.sync.aligned.m16n8k16.row.col.f32.bf16.bf16.f32 "
        "{%0,%1,%2,%3}, {%4,%5,%6,%7}, {%8,%9}, {%0,%1,%2,%3};"
        : "+f"(d[0]), "+f"(d[1]), "+f"(d[2]), "+f"(d[3])
        : "r"(a[0]), "r"(a[1]), "r"(a[2]), "r"(a[3]), "r"(b[0]), "r"(b[1]));
}

#define CPA16(dst, src) \
    asm volatile("cp.async.cg.shared.global [%0], [%1], 16;" :: "r"(dst), "l"(src))

// tanh via rational approx (FMA-only, no MUFU in the hot path)
__device__ __forceinline__ float fast_tanh(float x) {
    float cx = fminf(fmaxf(x, -7.90531110763549805f), 7.90531110763549805f);
    float x2 = cx * cx;
    float p = fmaf(x2, -2.76076847742355e-16f, 2.00018790482477e-13f);
    p = fmaf(p, x2, -8.60467152213735e-11f);
    p = fmaf(p, x2, 5.12229709037114e-08f);
    p = fmaf(p, x2, 1.48572235717979e-05f);
    p = fmaf(p, x2, 6.37261928875436e-04f);
    p = fmaf(p, x2, 4.89352455891786e-03f);
    p = p * cx;
    float q = fmaf(x2, 1.19825839466702e-06f, 1.18534705686654e-04f);
    q = fmaf(q, x2, 2.26843463243900e-03f);
    q = fmaf(q, x2, 4.89352518554385e-03f);
    float r = __uint_as_float(0x7EF127EAu - __float_as_uint(q));
    r = r * (2.0f - q * r);
    r = r * (2.0f - q * r);
    r = r * (2.0f - q * r);
    return p * r;
}

// ---------------------------------------------------------------------------
// 0. init
// ---------------------------------------------------------------------------
__global__ void init_kernel(float* __restrict__ out) {
    int i = blockIdx.x * blockDim.x + threadIdx.x;
    if (i < B_ * S_) g_scores[i] = 0.f;
    if (i < B_ * E_) out[i] = 0.f;
}

// ---------------------------------------------------------------------------
// 1. split-convert fp32 -> bf16 hi/lo (8 elems per thread)
// ---------------------------------------------------------------------------
__global__ __launch_bounds__(256)
void cvt_split_kernel(const float* __restrict__ src,
                      __nv_bfloat16* __restrict__ hi,
                      __nv_bfloat16* __restrict__ lo) {
    size_t idx = ((size_t)blockIdx.x * 256 + threadIdx.x) * 8;
    const float4* s4 = (const float4*)(src + idx);
    float4 f0 = s4[0], f1 = s4[1];
    float r0, r1, r2, r3, r4, r5, r6, r7;
    uint32_t h0 = pack_hi(f0.x, f0.y, r0, r1);
    uint32_t h1 = pack_hi(f0.z, f0.w, r2, r3);
    uint32_t h2 = pack_hi(f1.x, f1.y, r4, r5);
    uint32_t h3 = pack_hi(f1.z, f1.w, r6, r7);
    *(uint4*)(hi + idx) = make_uint4(h0, h1, h2, h3);
    *(uint4*)(lo + idx) = make_uint4(pack2(r0, r1), pack2(r2, r3),
                                     pack2(r4, r5), pack2(r6, r7));
}

// ---------------------------------------------------------------------------
// 2. dec_proj[b*D+d] = sum_k hidden[b,k] * Wd[d,k]
// ---------------------------------------------------------------------------
__global__ __launch_bounds__(256)
void dec_proj_kernel(const float* __restrict__ hidden, const float* __restrict__ Wd) {
    int warp = (blockIdx.x * blockDim.x + threadIdx.x) >> 5;
    int lane = threadIdx.x & 31;
    if (warp >= B_ * D_) return;
    int b = warp >> 10;
    int d = warp & (D_ - 1);
    const float4* h4 = (const float4*)(hidden + (size_t)b * D_);
    const float4* w4 = (const float4*)(Wd + (size_t)d * D_);
    float s = 0.f;
#pragma unroll
    for (int k = lane; k < D_ / 4; k += 32) {
        float4 a = h4[k], w = w4[k];
        s += a.x * w.x + a.y * w.y + a.z * w.z + a.w * w.w;
    }
#pragma unroll
    for (int o = 16; o; o >>= 1) s += __shfl_down_sync(0xffffffffu, s, o);
    if (!lane) g_dec[warp] = s;
}

// ---------------------------------------------------------------------------
// 3. Fused scores GEMM on HMMA: preconverted bf16 hi/lo, cp.async double-buffer
// ---------------------------------------------------------------------------
__global__ __launch_bounds__(256)
void score_mma_kernel(const float* __restrict__ v) {
    extern __shared__ __align__(1024) char smem[];
    const uint32_t sb = smem_u32(smem);

    const int tid = threadIdx.x;
    const int wid = tid >> 5;
    const int lane = tid & 31;
    const int wm = wid >> 1;          // 0..3
    const int wn = wid & 1;           // 0..1
    const int n_base = blockIdx.x * CTAN;
    const size_t m_base = (size_t)blockIdx.y * CTAM;

    // per-thread copy task: row lr (0..127), half lh -> two 16B groups per tile
    const int lr = tid >> 1;
    const int lh = tid & 1;
    const __nv_bfloat16* Ahi_r = g_ahi + (m_base + lr) * (size_t)K_;
    const __nv_bfloat16* Alo_r = g_alo + (m_base + lr) * (size_t)K_;
    const __nv_bfloat16* Bhi_r = g_bhi + (size_t)(n_base + lr) * K_;
    const __nv_bfloat16* Blo_r = g_blo + (size_t)(n_base + lr) * K_;
    const uint32_t o0 = sw_off(lr, lh * 2);
    const uint32_t o1 = sw_off(lr, lh * 2 + 1);
    const int g0 = lh * 16;            // elem offset of group lh*2 (8 bf16 each)
    const int g1 = lh * 16 + 8;

#define PREFETCH(c)                                                           \
    {                                                                         \
        uint32_t stb_ = sb + ((c) & 1) * STAGE_BYTES;                         \
        int ko_ = (c) * CKS;                                                  \
        CPA16(stb_ + OFF_AHI + o0, Ahi_r + ko_ + g0);                         \
        CPA16(stb_ + OFF_AHI + o1, Ahi_r + ko_ + g1);                         \
        CPA16(stb_ + OFF_ALO + o0, Alo_r + ko_ + g0);                         \
        CPA16(stb_ + OFF_ALO + o1, Alo_r + ko_ + g1);                         \
        CPA16(stb_ + OFF_BHI + o0, Bhi_r + ko_ + g0);                         \
        CPA16(stb_ + OFF_BHI + o1, Bhi_r + ko_ + g1);                         \
        CPA16(stb_ + OFF_BLO + o0, Blo_r + ko_ + g0);                         \
        CPA16(stb_ + OFF_BLO + o1, Blo_r + ko_ + g1);                         \
    }

    float acc[2][8][4];
#pragma unroll
    for (int mt = 0; mt < 2; mt++)
#pragma unroll
        for (int j = 0; j < 8; j++)
#pragma unroll
            for (int cc = 0; cc < 4; cc++) acc[mt][j][cc] = 0.f;

    // ldmatrix per-lane address components
    const uint32_t a_row = wm * 32 + (lane & 15);
    const uint32_t a_kg = (uint32_t)(lane >> 4);
    const uint32_t b_row_lo = wn * 64 + (lane & 7) + ((lane & 16) ? 8 : 0);
    const uint32_t b_kg = (uint32_t)((lane >> 3) & 1);

    PREFETCH(0);
    asm volatile("cp.async.commit_group;" ::: "memory");

    for (int c = 0; c < NCHUNK; c++) {
        if (c + 1 < NCHUNK) PREFETCH(c + 1);
        asm volatile("cp.async.commit_group;" ::: "memory");
        asm volatile("cp.async.wait_group 1;" ::: "memory");
        __syncthreads();

        const uint32_t stb = sb + (c & 1) * STAGE_BYTES;
#pragma unroll
        for (int ks = 0; ks < 2; ks++) {
            uint32_t ah[2][4], al[2][4];
#pragma unroll
            for (int mt = 0; mt < 2; mt++) {
                uint32_t off = sw_off(a_row + mt * 16, a_kg + 2 * ks);
                ldsm4(ah[mt], stb + OFF_AHI + off);
                ldsm4(al[mt], stb + OFF_ALO + off);
            }
#pragma unroll
            for (int half = 0; half < 2; half++) {
                uint32_t bh[4][2], bl[4][2];
#pragma unroll
                for (int j2 = 0; j2 < 2; j2++) {
                    uint32_t off = sw_off(b_row_lo + (half * 2 + j2) * 16, b_kg + 2 * ks);
                    uint32_t t[4];
                    ldsm4(t, stb + OFF_BHI + off);
                    bh[j2 * 2][0] = t[0]; bh[j2 * 2][1] = t[1];
                    bh[j2 * 2 + 1][0] = t[2]; bh[j2 * 2 + 1][1] = t[3];
                    ldsm4(t, stb + OFF_BLO + off);
                    bl[j2 * 2][0] = t[0]; bl[j2 * 2][1] = t[1];
                    bl[j2 * 2 + 1][0] = t[2]; bl[j2 * 2 + 1][1] = t[3];
                }
#pragma unroll
                for (int mt = 0; mt < 2; mt++)
#pragma unroll
                    for (int j = 0; j < 4; j++) {
                        float* d = acc[mt][half * 4 + j];
                        mma_bf16(d, ah[mt], bh[j]);   // hi*hi
                        mma_bf16(d, ah[mt], bl[j]);   // hi*lo
                        mma_bf16(d, al[mt], bh[j]);   // lo*hi
                    }
            }
        }
        __syncthreads();   // stage (c&1) free for reuse at iteration c+1's prefetch
    }

    // ---- epilogue: stage dec tile + v into smem, tanh + v-dot, reduce ----
    float* sdec = (float*)smem;            // [32][128] = 16KB
    float* sv = (float*)(smem + 16384);    // [128]
    for (int i = tid; i < B_ * CTAN; i += 256) {
        int b = i >> 7, n = i & (CTAN - 1);
        sdec[b * CTAN + n] = g_dec[b * D_ + n_base + n];
    }
    if (tid < CTAN) sv[tid] = v[n_base + tid];
    __syncthreads();

#pragma unroll
    for (int mt = 0; mt < 2; mt++) {
        int rowA = wm * 32 + mt * 16 + (lane >> 2);
        int b0 = rowA & 31, b1 = (rowA + 8) & 31;
        float s0 = 0.f, s1 = 0.f;
#pragma unroll
        for (int j = 0; j < 8; j++) {
            int nc = wn * 64 + j * 8 + (lane & 3) * 2;
            float v0 = sv[nc], v1 = sv[nc + 1];
            s0 = fmaf(fast_tanh(acc[mt][j][0] + sdec[b0 * CTAN + nc]), v0, s0);
            s0 = fmaf(fast_tanh(acc[mt][j][1] + sdec[b0 * CTAN + nc + 1]), v1, s0);
            s1 = fmaf(fast_tanh(acc[mt][j][2] + sdec[b1 * CTAN + nc]), v0, s1);
            s1 = fmaf(fast_tanh(acc[mt][j][3] + sdec[b1 * CTAN + nc + 1]), v1, s1);
        }
        s0 += __shfl_xor_sync(0xffffffffu, s0, 1);
        s0 += __shfl_xor_sync(0xffffffffu, s0, 2);
        s1 += __shfl_xor_sync(0xffffffffu, s1, 1);
        s1 += __shfl_xor_sync(0xffffffffu, s1, 2);
        if ((lane & 3) == 0) {
            size_t m0 = m_base + rowA;
            size_t m1 = m0 + 8;
            atomicAdd(&g_scores[(m0 & 31) * S_ + (m0 >> 5)], s0);
            atomicAdd(&g_scores[(m1 & 31) * S_ + (m1 >> 5)], s1);
        }
    }
}

// ---------------------------------------------------------------------------
// 4. softmax over S per batch
// ---------------------------------------------------------------------------
__global__ __launch_bounds__(256)
void softmax_kernel(float* __restrict__ wout) {
    int b = blockIdx.x;
    int tid = threadIdx.x;
    __shared__ float sm[256];

    float vals[8];
    float mx = -1e30f;
#pragma unroll
    for (int i = 0; i < 8; i++) {
        vals[i] = g_scores[b * S_ + tid + i * 256];
        mx = fmaxf(mx, vals[i]);
    }
    sm[tid] = mx; __syncthreads();
    for (int o = 128; o; o >>= 1) {
        if (tid < o) sm[tid] = fmaxf(sm[tid], sm[tid + o]);
        __syncthreads();
    }
    mx = sm[0]; __syncthreads();

    float sum = 0.f;
#pragma unroll
    for (int i = 0; i < 8; i++) { vals[i] = expf(vals[i] - mx); sum += vals[i]; }
    sm[tid] = sum; __syncthreads();
    for (int o = 128; o; o >>= 1) {
        if (tid < o) sm[tid] += sm[tid + o];
        __syncthreads();
    }
    float inv = 1.f / sm[0];
#pragma unroll
    for (int i = 0; i < 8; i++) wout[b * S_ + tid + i * 256] = vals[i] * inv;
}

// ---------------------------------------------------------------------------
// 5. context[b,e] = sum_s w[b,s] * enc[s,b,e]
// ---------------------------------------------------------------------------
#define CSPLIT 8
__global__ __launch_bounds__(256)
void context_kernel(const float* __restrict__ enc, const float* __restrict__ w,
                    float* __restrict__ ctx) {
    int e = blockIdx.x * 256 + threadIdx.x;
    int b = blockIdx.y;
    int s0 = blockIdx.z * (S_ / CSPLIT);
    const float* base = enc + (size_t)b * E_ + e;
    float acc0 = 0.f, acc1 = 0.f, acc2 = 0.f, acc3 = 0.f;
#pragma unroll 2
    for (int s = s0; s < s0 + S_ / CSPLIT; s += 4) {
        acc0 += w[b * S_ + s + 0] * base[(size_t)(s + 0) * (B_ * E_)];
        acc1 += w[b * S_ + s + 1] * base[(size_t)(s + 1) * (B_ * E_)];
        acc2 += w[b * S_ + s + 2] * base[(size_t)(s + 2) * (B_ * E_)];
        acc3 += w[b * S_ + s + 3] * base[(size_t)(s + 3) * (B_ * E_)];
    }
    atomicAdd(&ctx[b * E_ + e], (acc0 + acc1) + (acc2 + acc3));
}

// ---------------------------------------------------------------------------
extern "C" void kernel_launch(void* const* d_in, const int* in_sizes, int n_in,
                              void* d_out, int out_size) {
    const float* hidden = (const float*)d_in[0];  // [B,D]
    const float* enc    = (const float*)d_in[1];  // [S,B,E]
    const float* We     = (const float*)d_in[2];  // [D,E]
    const float* Wd     = (const float*)d_in[3];  // [D,D]
    const float* v      = (const float*)d_in[4];  // [D]
    float* out = (float*)d_out;                   // [B*E context | B*S weights]
    float* wout = out + B_ * E_;

    cudaFuncSetAttribute(score_mma_kernel,
                         cudaFuncAttributeMaxDynamicSharedMemorySize, SMEM_BYTES);

    __nv_bfloat16 *ahi, *alo, *bhi, *blo;
    cudaGetSymbolAddress((void**)&ahi, g_ahi);
    cudaGetSymbolAddress((void**)&alo, g_alo);
    cudaGetSymbolAddress((void**)&bhi, g_bhi);
    cudaGetSymbolAddress((void**)&blo, g_blo);

    init_kernel<<<(B_ * S_ + 255) / 256, 256>>>(out);
    cvt_split_kernel<<<(size_t)M_ * K_ / 2048, 256>>>(enc, ahi, alo);
    cvt_split_kernel<<<(size_t)D_ * K_ / 2048, 256>>>(We, bhi, blo);
    dec_proj_kernel<<<(B_ * D_ * 32 + 255) / 256, 256>>>(hidden, Wd);
    score_mma_kernel<<<dim3(NT, MT), 256, SMEM_BYTES>>>(v);
    softmax_kernel<<<B_, 256>>>(wout);
    context_kernel<<<dim3(E_ / 256, B_, CSPLIT), 256>>>(enc, wout, out);
}

// round 6
// speedup vs baseline: 2.9071x; 1.4358x over previous
#include <cuda_runtime.h>
#include <cuda_fp16.h>
#include <math.h>
#include <stdint.h>

#define B_ 32
#define S_ 2048
#define E_ 1024
#define D_ 1024
#define K_ 1024
#define M_ (S_ * B_)   // 65536

// GEMM tiling
#define CTAM 128
#define CTAN 128
#define CKS 32                 // K per chunk
#define NCHUNK (K_ / CKS)      // 32
#define NT (D_ / CTAN)         // 8
#define MT (M_ / CTAM)         // 512

// SMEM per stage: 3 tiles of 128 rows x 64B = 8KB each
#define OFF_AH 0
#define OFF_BH 8192
#define OFF_BL 16384
#define STAGE_BYTES 24576
#define SMEM_BYTES (2 * STAGE_BYTES)   // 48KB dynamic

__device__ float g_scores[B_ * S_];
__device__ float g_dec[B_ * D_];
__device__ __half g_ah[(size_t)M_ * K_];   // fp16(A)
__device__ __half g_bh[(size_t)D_ * K_];   // fp16(B)
__device__ __half g_bl[(size_t)D_ * K_];   // fp16(B - fp16(B))

// ---------------------------------------------------------------------------
__device__ __forceinline__ uint32_t smem_u32(const void* p) {
    uint32_t a;
    asm("{ .reg .u64 t; cvta.to.shared.u64 t, %1; cvt.u32.u64 %0, t; }" : "=r"(a) : "l"(p));
    return a;
}

// 16B-group swizzled offset within a 128x64B tile
__device__ __forceinline__ uint32_t sw_off(uint32_t row, uint32_t g) {
    return (row << 6) | (((g ^ row) & 3u) << 4);
}

__device__ __forceinline__ void ldsm4(uint32_t* r, uint32_t addr) {
    asm volatile("ldmatrix.sync.aligned.m8n8.x4.shared.b16 {%0,%1,%2,%3}, [%4];"
                 : "=r"(r[0]), "=r"(r[1]), "=r"(r[2]), "=r"(r[3]) : "r"(addr));
}

__device__ __forceinline__ void mma_f16(float* d, const uint32_t* a, const uint32_t* b) {
    asm volatile(
        "mma.sync.aligned.m16n8k16.row.col.f32.f16.f16.f32 "
        "{%0,%1,%2,%3}, {%4,%5,%6,%7}, {%8,%9}, {%0,%1,%2,%3};"
        : "+f"(d[0]), "+f"(d[1]), "+f"(d[2]), "+f"(d[3])
        : "r"(a[0]), "r"(a[1]), "r"(a[2]), "r"(a[3]), "r"(b[0]), "r"(b[1]));
}

#define CPA16(dst, src) \
    asm volatile("cp.async.cg.shared.global [%0], [%1], 16;" :: "r"(dst), "l"(src))

// tanh via rational approx (FMA-only, no MUFU in the hot path)
__device__ __forceinline__ float fast_tanh(float x) {
    float cx = fminf(fmaxf(x, -7.90531110763549805f), 7.90531110763549805f);
    float x2 = cx * cx;
    float p = fmaf(x2, -2.76076847742355e-16f, 2.00018790482477e-13f);
    p = fmaf(p, x2, -8.60467152213735e-11f);
    p = fmaf(p, x2, 5.12229709037114e-08f);
    p = fmaf(p, x2, 1.48572235717979e-05f);
    p = fmaf(p, x2, 6.37261928875436e-04f);
    p = fmaf(p, x2, 4.89352455891786e-03f);
    p = p * cx;
    float q = fmaf(x2, 1.19825839466702e-06f, 1.18534705686654e-04f);
    q = fmaf(q, x2, 2.26843463243900e-03f);
    q = fmaf(q, x2, 4.89352518554385e-03f);
    float r = __uint_as_float(0x7EF127EAu - __float_as_uint(q));
    r = r * (2.0f - q * r);
    r = r * (2.0f - q * r);
    r = r * (2.0f - q * r);
    return p * r;
}

// ---------------------------------------------------------------------------
// 0. init
// ---------------------------------------------------------------------------
__global__ void init_kernel(float* __restrict__ out) {
    int i = blockIdx.x * blockDim.x + threadIdx.x;
    if (i < B_ * S_) g_scores[i] = 0.f;
    if (i < B_ * E_) out[i] = 0.f;
}

// ---------------------------------------------------------------------------
// 1a. convert A -> fp16 (8 elems/thread)
// ---------------------------------------------------------------------------
__global__ __launch_bounds__(256)
void cvt_a_kernel(const float* __restrict__ src, __half* __restrict__ dst) {
    size_t idx = ((size_t)blockIdx.x * 256 + threadIdx.x) * 8;
    const float4* s4 = (const float4*)(src + idx);
    float4 f0 = s4[0], f1 = s4[1];
    __half2 h[4];
    h[0] = __floats2half2_rn(f0.x, f0.y);
    h[1] = __floats2half2_rn(f0.z, f0.w);
    h[2] = __floats2half2_rn(f1.x, f1.y);
    h[3] = __floats2half2_rn(f1.z, f1.w);
    *(uint4*)(dst + idx) = *(uint4*)h;
}

// ---------------------------------------------------------------------------
// 1b. split-convert B -> fp16 hi/lo (8 elems/thread)
// ---------------------------------------------------------------------------
__global__ __launch_bounds__(256)
void cvt_b_kernel(const float* __restrict__ src,
                  __half* __restrict__ hi, __half* __restrict__ lo) {
    size_t idx = ((size_t)blockIdx.x * 256 + threadIdx.x) * 8;
    float f[8];
    *(float4*)(f) = *(const float4*)(src + idx);
    *(float4*)(f + 4) = *(const float4*)(src + idx + 4);
    __half2 h[4], l[4];
#pragma unroll
    for (int i = 0; i < 4; i++) {
        __half a = __float2half_rn(f[2 * i]);
        __half b = __float2half_rn(f[2 * i + 1]);
        h[i] = __halves2half2(a, b);
        l[i] = __floats2half2_rn(f[2 * i] - __half2float(a),
                                 f[2 * i + 1] - __half2float(b));
    }
    *(uint4*)(hi + idx) = *(uint4*)h;
    *(uint4*)(lo + idx) = *(uint4*)l;
}

// ---------------------------------------------------------------------------
// 2. dec_proj[b*D+d] = sum_k hidden[b,k] * Wd[d,k]
// ---------------------------------------------------------------------------
__global__ __launch_bounds__(256)
void dec_proj_kernel(const float* __restrict__ hidden, const float* __restrict__ Wd) {
    int warp = (blockIdx.x * blockDim.x + threadIdx.x) >> 5;
    int lane = threadIdx.x & 31;
    if (warp >= B_ * D_) return;
    int b = warp >> 10;
    int d = warp & (D_ - 1);
    const float4* h4 = (const float4*)(hidden + (size_t)b * D_);
    const float4* w4 = (const float4*)(Wd + (size_t)d * D_);
    float s = 0.f;
#pragma unroll
    for (int k = lane; k < D_ / 4; k += 32) {
        float4 a = h4[k], w = w4[k];
        s += a.x * w.x + a.y * w.y + a.z * w.z + a.w * w.w;
    }
#pragma unroll
    for (int o = 16; o; o >>= 1) s += __shfl_down_sync(0xffffffffu, s, o);
    if (!lane) g_dec[warp] = s;
}

// ---------------------------------------------------------------------------
// 3. Fused scores GEMM: fp16 2-pass (Ah*Bh + Ah*Bl), cp.async double-buffer
// ---------------------------------------------------------------------------
__global__ __launch_bounds__(256)
void score_mma_kernel(const float* __restrict__ v) {
    extern __shared__ __align__(1024) char smem[];
    const uint32_t sb = smem_u32(smem);

    const int tid = threadIdx.x;
    const int wid = tid >> 5;
    const int lane = tid & 31;
    const int wm = wid >> 1;          // 0..3
    const int wn = wid & 1;           // 0..1
    const int n_base = blockIdx.x * CTAN;
    const size_t m_base = (size_t)blockIdx.y * CTAM;

    // per-thread copy task: row lr (0..127), half lh -> two 16B groups per tile
    const int lr = tid >> 1;
    const int lh = tid & 1;
    const __half* Ah_r = g_ah + (m_base + lr) * (size_t)K_;
    const __half* Bh_r = g_bh + (size_t)(n_base + lr) * K_;
    const __half* Bl_r = g_bl + (size_t)(n_base + lr) * K_;
    const uint32_t o0 = sw_off(lr, lh * 2);
    const uint32_t o1 = sw_off(lr, lh * 2 + 1);
    const int g0 = lh * 16;            // elem offset of group lh*2 (8 fp16 each)
    const int g1 = lh * 16 + 8;

#define PREFETCH(c)                                                           \
    {                                                                         \
        uint32_t stb_ = sb + ((c) & 1) * STAGE_BYTES;                         \
        int ko_ = (c) * CKS;                                                  \
        CPA16(stb_ + OFF_AH + o0, Ah_r + ko_ + g0);                           \
        CPA16(stb_ + OFF_AH + o1, Ah_r + ko_ + g1);                           \
        CPA16(stb_ + OFF_BH + o0, Bh_r + ko_ + g0);                           \
        CPA16(stb_ + OFF_BH + o1, Bh_r + ko_ + g1);                           \
        CPA16(stb_ + OFF_BL + o0, Bl_r + ko_ + g0);                           \
        CPA16(stb_ + OFF_BL + o1, Bl_r + ko_ + g1);                           \
    }

    float acc[2][8][4];
#pragma unroll
    for (int mt = 0; mt < 2; mt++)
#pragma unroll
        for (int j = 0; j < 8; j++)
#pragma unroll
            for (int cc = 0; cc < 4; cc++) acc[mt][j][cc] = 0.f;

    // ldmatrix per-lane address components
    const uint32_t a_row = wm * 32 + (lane & 15);
    const uint32_t a_kg = (uint32_t)(lane >> 4);
    const uint32_t b_row_lo = wn * 64 + (lane & 7) + ((lane & 16) ? 8 : 0);
    const uint32_t b_kg = (uint32_t)((lane >> 3) & 1);

    PREFETCH(0);
    asm volatile("cp.async.commit_group;" ::: "memory");

    for (int c = 0; c < NCHUNK; c++) {
        if (c + 1 < NCHUNK) PREFETCH(c + 1);
        asm volatile("cp.async.commit_group;" ::: "memory");
        asm volatile("cp.async.wait_group 1;" ::: "memory");
        __syncthreads();

        const uint32_t stb = sb + (c & 1) * STAGE_BYTES;
#pragma unroll
        for (int ks = 0; ks < 2; ks++) {
            uint32_t ah[2][4];
#pragma unroll
            for (int mt = 0; mt < 2; mt++) {
                uint32_t off = sw_off(a_row + mt * 16, a_kg + 2 * ks);
                ldsm4(ah[mt], stb + OFF_AH + off);
            }
#pragma unroll
            for (int half = 0; half < 2; half++) {
                uint32_t bh[4][2], bl[4][2];
#pragma unroll
                for (int j2 = 0; j2 < 2; j2++) {
                    uint32_t off = sw_off(b_row_lo + (half * 2 + j2) * 16, b_kg + 2 * ks);
                    uint32_t t[4];
                    ldsm4(t, stb + OFF_BH + off);
                    bh[j2 * 2][0] = t[0]; bh[j2 * 2][1] = t[1];
                    bh[j2 * 2 + 1][0] = t[2]; bh[j2 * 2 + 1][1] = t[3];
                    ldsm4(t, stb + OFF_BL + off);
                    bl[j2 * 2][0] = t[0]; bl[j2 * 2][1] = t[1];
                    bl[j2 * 2 + 1][0] = t[2]; bl[j2 * 2 + 1][1] = t[3];
                }
#pragma unroll
                for (int mt = 0; mt < 2; mt++)
#pragma unroll
                    for (int j = 0; j < 4; j++) {
                        float* d = acc[mt][half * 4 + j];
                        mma_f16(d, ah[mt], bh[j]);   // Ah*Bh
                        mma_f16(d, ah[mt], bl[j]);   // Ah*Bl
                    }
            }
        }
        __syncthreads();   // stage (c&1) free for reuse at iteration c+1's prefetch
    }

    // ---- epilogue: stage dec tile + v into smem, tanh + v-dot, reduce ----
    float* sdec = (float*)smem;            // [32][128] = 16KB
    float* sv = (float*)(smem + 16384);    // [128]
    for (int i = tid; i < B_ * CTAN; i += 256) {
        int b = i >> 7, n = i & (CTAN - 1);
        sdec[b * CTAN + n] = g_dec[b * D_ + n_base + n];
    }
    if (tid < CTAN) sv[tid] = v[n_base + tid];
    __syncthreads();

#pragma unroll
    for (int mt = 0; mt < 2; mt++) {
        int rowA = wm * 32 + mt * 16 + (lane >> 2);
        int b0 = rowA & 31, b1 = (rowA + 8) & 31;
        float s0 = 0.f, s1 = 0.f;
#pragma unroll
        for (int j = 0; j < 8; j++) {
            int nc = wn * 64 + j * 8 + (lane & 3) * 2;
            float v0 = sv[nc], v1 = sv[nc + 1];
            s0 = fmaf(fast_tanh(acc[mt][j][0] + sdec[b0 * CTAN + nc]), v0, s0);
            s0 = fmaf(fast_tanh(acc[mt][j][1] + sdec[b0 * CTAN + nc + 1]), v1, s0);
            s1 = fmaf(fast_tanh(acc[mt][j][2] + sdec[b1 * CTAN + nc]), v0, s1);
            s1 = fmaf(fast_tanh(acc[mt][j][3] + sdec[b1 * CTAN + nc + 1]), v1, s1);
        }
        s0 += __shfl_xor_sync(0xffffffffu, s0, 1);
        s0 += __shfl_xor_sync(0xffffffffu, s0, 2);
        s1 += __shfl_xor_sync(0xffffffffu, s1, 1);
        s1 += __shfl_xor_sync(0xffffffffu, s1, 2);
        if ((lane & 3) == 0) {
            size_t m0 = m_base + rowA;
            size_t m1 = m0 + 8;
            atomicAdd(&g_scores[(m0 & 31) * S_ + (m0 >> 5)], s0);
            atomicAdd(&g_scores[(m1 & 31) * S_ + (m1 >> 5)], s1);
        }
    }
}

// ---------------------------------------------------------------------------
// 4. softmax over S per batch
// ---------------------------------------------------------------------------
__global__ __launch_bounds__(256)
void softmax_kernel(float* __restrict__ wout) {
    int b = blockIdx.x;
    int tid = threadIdx.x;
    __shared__ float sm[256];

    float vals[8];
    float mx = -1e30f;
#pragma unroll
    for (int i = 0; i < 8; i++) {
        vals[i] = g_scores[b * S_ + tid + i * 256];
        mx = fmaxf(mx, vals[i]);
    }
    sm[tid] = mx; __syncthreads();
    for (int o = 128; o; o >>= 1) {
        if (tid < o) sm[tid] = fmaxf(sm[tid], sm[tid + o]);
        __syncthreads();
    }
    mx = sm[0]; __syncthreads();

    float sum = 0.f;
#pragma unroll
    for (int i = 0; i < 8; i++) { vals[i] = expf(vals[i] - mx); sum += vals[i]; }
    sm[tid] = sum; __syncthreads();
    for (int o = 128; o; o >>= 1) {
        if (tid < o) sm[tid] += sm[tid + o];
        __syncthreads();
    }
    float inv = 1.f / sm[0];
#pragma unroll
    for (int i = 0; i < 8; i++) wout[b * S_ + tid + i * 256] = vals[i] * inv;
}

// ---------------------------------------------------------------------------
// 5. context[b,e] = sum_s w[b,s] * enc[s,b,e]
// ---------------------------------------------------------------------------
#define CSPLIT 8
__global__ __launch_bounds__(256)
void context_kernel(const float* __restrict__ enc, const float* __restrict__ w,
                    float* __restrict__ ctx) {
    int e = blockIdx.x * 256 + threadIdx.x;
    int b = blockIdx.y;
    int s0 = blockIdx.z * (S_ / CSPLIT);
    const float* base = enc + (size_t)b * E_ + e;
    float acc0 = 0.f, acc1 = 0.f, acc2 = 0.f, acc3 = 0.f;
#pragma unroll 2
    for (int s = s0; s < s0 + S_ / CSPLIT; s += 4) {
        acc0 += w[b * S_ + s + 0] * base[(size_t)(s + 0) * (B_ * E_)];
        acc1 += w[b * S_ + s + 1] * base[(size_t)(s + 1) * (B_ * E_)];
        acc2 += w[b * S_ + s + 2] * base[(size_t)(s + 2) * (B_ * E_)];
        acc3 += w[b * S_ + s + 3] * base[(size_t)(s + 3) * (B_ * E_)];
    }
    atomicAdd(&ctx[b * E_ + e], (acc0 + acc1) + (acc2 + acc3));
}

// ---------------------------------------------------------------------------
extern "C" void kernel_launch(void* const* d_in, const int* in_sizes, int n_in,
                              void* d_out, int out_size) {
    const float* hidden = (const float*)d_in[0];  // [B,D]
    const float* enc    = (const float*)d_in[1];  // [S,B,E]
    const float* We     = (const float*)d_in[2];  // [D,E]
    const float* Wd     = (const float*)d_in[3];  // [D,D]
    const float* v      = (const float*)d_in[4];  // [D]
    float* out = (float*)d_out;                   // [B*E context | B*S weights]
    float* wout = out + B_ * E_;

    cudaFuncSetAttribute(score_mma_kernel,
                         cudaFuncAttributeMaxDynamicSharedMemorySize, SMEM_BYTES);

    __half *ah, *bh, *bl;
    cudaGetSymbolAddress((void**)&ah, g_ah);
    cudaGetSymbolAddress((void**)&bh, g_bh);
    cudaGetSymbolAddress((void**)&bl, g_bl);

    init_kernel<<<(B_ * S_ + 255) / 256, 256>>>(out);
    cvt_a_kernel<<<(size_t)M_ * K_ / 2048, 256>>>(enc, ah);
    cvt_b_kernel<<<(size_t)D_ * K_ / 2048, 256>>>(We, bh, bl);
    dec_proj_kernel<<<(B_ * D_ * 32 + 255) / 256, 256>>>(hidden, Wd);
    score_mma_kernel<<<dim3(NT, MT), 256, SMEM_BYTES>>>(v);
    softmax_kernel<<<B_, 256>>>(wout);
    context_kernel<<<dim3(E_ / 256, B_, CSPLIT), 256>>>(enc, wout, out);
}

// round 7
// speedup vs baseline: 4.2461x; 1.4606x over previous
#include <cuda_runtime.h>
#include <cuda_fp16.h>
#include <math.h>
#include <stdint.h>

#define B_ 32
#define S_ 2048
#define E_ 1024
#define D_ 1024
#define K_ 1024
#define M_ (S_ * B_)   // 65536

// GEMM tiling
#define CTAM 128
#define CTAN 128
#define CKS 32                 // K per chunk
#define NCHUNK (K_ / CKS)      // 32
#define NT (D_ / CTAN)         // 8
#define MT (M_ / CTAM)         // 512

// SMEM per stage: 2 tiles of 128 rows x 64B = 8KB each
#define OFF_AH 0
#define OFF_BH 8192
#define STAGE_BYTES 16384
#define SMEM_BYTES (2 * STAGE_BYTES)   // 32KB dynamic

__device__ float g_scores[B_ * S_];
__device__ float g_dec[B_ * D_];
__device__ __half g_ah[(size_t)M_ * K_];   // fp16(A)
__device__ __half g_bh[(size_t)D_ * K_];   // fp16(B)

// ---------------------------------------------------------------------------
__device__ __forceinline__ uint32_t smem_u32(const void* p) {
    uint32_t a;
    asm("{ .reg .u64 t; cvta.to.shared.u64 t, %1; cvt.u32.u64 %0, t; }" : "=r"(a) : "l"(p));
    return a;
}

// 16B-group swizzled offset within a 128x64B tile
__device__ __forceinline__ uint32_t sw_off(uint32_t row, uint32_t g) {
    return (row << 6) | (((g ^ row) & 3u) << 4);
}

__device__ __forceinline__ void ldsm4(uint32_t* r, uint32_t addr) {
    asm volatile("ldmatrix.sync.aligned.m8n8.x4.shared.b16 {%0,%1,%2,%3}, [%4];"
                 : "=r"(r[0]), "=r"(r[1]), "=r"(r[2]), "=r"(r[3]) : "r"(addr));
}

__device__ __forceinline__ void mma_f16(float* d, const uint32_t* a, const uint32_t* b) {
    asm volatile(
        "mma.sync.aligned.m16n8k16.row.col.f32.f16.f16.f32 "
        "{%0,%1,%2,%3}, {%4,%5,%6,%7}, {%8,%9}, {%0,%1,%2,%3};"
        : "+f"(d[0]), "+f"(d[1]), "+f"(d[2]), "+f"(d[3])
        : "r"(a[0]), "r"(a[1]), "r"(a[2]), "r"(a[3]), "r"(b[0]), "r"(b[1]));
}

#define CPA16(dst, src) \
    asm volatile("cp.async.cg.shared.global [%0], [%1], 16;" :: "r"(dst), "l"(src))

// tanh via rational approx (FMA-only, no MUFU in the hot path)
__device__ __forceinline__ float fast_tanh(float x) {
    float cx = fminf(fmaxf(x, -7.90531110763549805f), 7.90531110763549805f);
    float x2 = cx * cx;
    float p = fmaf(x2, -2.76076847742355e-16f, 2.00018790482477e-13f);
    p = fmaf(p, x2, -8.60467152213735e-11f);
    p = fmaf(p, x2, 5.12229709037114e-08f);
    p = fmaf(p, x2, 1.48572235717979e-05f);
    p = fmaf(p, x2, 6.37261928875436e-04f);
    p = fmaf(p, x2, 4.89352455891786e-03f);
    p = p * cx;
    float q = fmaf(x2, 1.19825839466702e-06f, 1.18534705686654e-04f);
    q = fmaf(q, x2, 2.26843463243900e-03f);
    q = fmaf(q, x2, 4.89352518554385e-03f);
    float r = __uint_as_float(0x7EF127EAu - __float_as_uint(q));
    r = r * (2.0f - q * r);
    r = r * (2.0f - q * r);
    r = r * (2.0f - q * r);
    return p * r;
}

// ---------------------------------------------------------------------------
// 0. init
// ---------------------------------------------------------------------------
__global__ void init_kernel(float* __restrict__ out) {
    int i = blockIdx.x * blockDim.x + threadIdx.x;
    if (i < B_ * S_) g_scores[i] = 0.f;
    if (i < B_ * E_) out[i] = 0.f;
}

// ---------------------------------------------------------------------------
// 1. convert fp32 -> fp16 (8 elems/thread)
// ---------------------------------------------------------------------------
__global__ __launch_bounds__(256)
void cvt_h_kernel(const float* __restrict__ src, __half* __restrict__ dst) {
    size_t idx = ((size_t)blockIdx.x * 256 + threadIdx.x) * 8;
    const float4* s4 = (const float4*)(src + idx);
    float4 f0 = s4[0], f1 = s4[1];
    __half2 h[4];
    h[0] = __floats2half2_rn(f0.x, f0.y);
    h[1] = __floats2half2_rn(f0.z, f0.w);
    h[2] = __floats2half2_rn(f1.x, f1.y);
    h[3] = __floats2half2_rn(f1.z, f1.w);
    *(uint4*)(dst + idx) = *(uint4*)h;
}

// ---------------------------------------------------------------------------
// 2. dec_proj[b*D+d] = sum_k hidden[b,k] * Wd[d,k]
// ---------------------------------------------------------------------------
__global__ __launch_bounds__(256)
void dec_proj_kernel(const float* __restrict__ hidden, const float* __restrict__ Wd) {
    int warp = (blockIdx.x * blockDim.x + threadIdx.x) >> 5;
    int lane = threadIdx.x & 31;
    if (warp >= B_ * D_) return;
    int b = warp >> 10;
    int d = warp & (D_ - 1);
    const float4* h4 = (const float4*)(hidden + (size_t)b * D_);
    const float4* w4 = (const float4*)(Wd + (size_t)d * D_);
    float s = 0.f;
#pragma unroll
    for (int k = lane; k < D_ / 4; k += 32) {
        float4 a = h4[k], w = w4[k];
        s += a.x * w.x + a.y * w.y + a.z * w.z + a.w * w.w;
    }
#pragma unroll
    for (int o = 16; o; o >>= 1) s += __shfl_down_sync(0xffffffffu, s, o);
    if (!lane) g_dec[warp] = s;
}

// ---------------------------------------------------------------------------
// 3. Fused scores GEMM: single-pass fp16, cp.async double-buffer
// ---------------------------------------------------------------------------
__global__ __launch_bounds__(256)
void score_mma_kernel(const float* __restrict__ v) {
    extern __shared__ __align__(1024) char smem[];
    const uint32_t sb = smem_u32(smem);

    const int tid = threadIdx.x;
    const int wid = tid >> 5;
    const int lane = tid & 31;
    const int wm = wid >> 1;          // 0..3
    const int wn = wid & 1;           // 0..1
    const int n_base = blockIdx.x * CTAN;
    const size_t m_base = (size_t)blockIdx.y * CTAM;

    // per-thread copy task: row lr (0..127), half lh -> two 16B groups per tile
    const int lr = tid >> 1;
    const int lh = tid & 1;
    const __half* Ah_r = g_ah + (m_base + lr) * (size_t)K_;
    const __half* Bh_r = g_bh + (size_t)(n_base + lr) * K_;
    const uint32_t o0 = sw_off(lr, lh * 2);
    const uint32_t o1 = sw_off(lr, lh * 2 + 1);
    const int g0 = lh * 16;            // elem offset of group lh*2 (8 fp16 each)
    const int g1 = lh * 16 + 8;

#define PREFETCH(c)                                                           \
    {                                                                         \
        uint32_t stb_ = sb + ((c) & 1) * STAGE_BYTES;                         \
        int ko_ = (c) * CKS;                                                  \
        CPA16(stb_ + OFF_AH + o0, Ah_r + ko_ + g0);                           \
        CPA16(stb_ + OFF_AH + o1, Ah_r + ko_ + g1);                           \
        CPA16(stb_ + OFF_BH + o0, Bh_r + ko_ + g0);                           \
        CPA16(stb_ + OFF_BH + o1, Bh_r + ko_ + g1);                           \
    }

    float acc[2][8][4];
#pragma unroll
    for (int mt = 0; mt < 2; mt++)
#pragma unroll
        for (int j = 0; j < 8; j++)
#pragma unroll
            for (int cc = 0; cc < 4; cc++) acc[mt][j][cc] = 0.f;

    // ldmatrix per-lane address components
    const uint32_t a_row = wm * 32 + (lane & 15);
    const uint32_t a_kg = (uint32_t)(lane >> 4);
    const uint32_t b_row_lo = wn * 64 + (lane & 7) + ((lane & 16) ? 8 : 0);
    const uint32_t b_kg = (uint32_t)((lane >> 3) & 1);

    PREFETCH(0);
    asm volatile("cp.async.commit_group;" ::: "memory");

    for (int c = 0; c < NCHUNK; c++) {
        if (c + 1 < NCHUNK) PREFETCH(c + 1);
        asm volatile("cp.async.commit_group;" ::: "memory");
        asm volatile("cp.async.wait_group 1;" ::: "memory");
        __syncthreads();

        const uint32_t stb = sb + (c & 1) * STAGE_BYTES;
#pragma unroll
        for (int ks = 0; ks < 2; ks++) {
            uint32_t ah[2][4];
#pragma unroll
            for (int mt = 0; mt < 2; mt++) {
                uint32_t off = sw_off(a_row + mt * 16, a_kg + 2 * ks);
                ldsm4(ah[mt], stb + OFF_AH + off);
            }
#pragma unroll
            for (int half = 0; half < 2; half++) {
                uint32_t bh[4][2];
#pragma unroll
                for (int j2 = 0; j2 < 2; j2++) {
                    uint32_t off = sw_off(b_row_lo + (half * 2 + j2) * 16, b_kg + 2 * ks);
                    uint32_t t[4];
                    ldsm4(t, stb + OFF_BH + off);
                    bh[j2 * 2][0] = t[0]; bh[j2 * 2][1] = t[1];
                    bh[j2 * 2 + 1][0] = t[2]; bh[j2 * 2 + 1][1] = t[3];
                }
#pragma unroll
                for (int mt = 0; mt < 2; mt++)
#pragma unroll
                    for (int j = 0; j < 4; j++)
                        mma_f16(acc[mt][half * 4 + j], ah[mt], bh[j]);
            }
        }
        __syncthreads();   // stage (c&1) free for reuse at iteration c+1's prefetch
    }

    // ---- epilogue: stage dec tile + v into smem, tanh + v-dot, reduce ----
    float* sdec = (float*)smem;            // [32][128] = 16KB
    float* sv = (float*)(smem + 16384);    // [128]
    for (int i = tid; i < B_ * CTAN; i += 256) {
        int b = i >> 7, n = i & (CTAN - 1);
        sdec[b * CTAN + n] = g_dec[b * D_ + n_base + n];
    }
    if (tid < CTAN) sv[tid] = v[n_base + tid];
    __syncthreads();

#pragma unroll
    for (int mt = 0; mt < 2; mt++) {
        int rowA = wm * 32 + mt * 16 + (lane >> 2);
        int b0 = rowA & 31, b1 = (rowA + 8) & 31;
        float s0 = 0.f, s1 = 0.f;
#pragma unroll
        for (int j = 0; j < 8; j++) {
            int nc = wn * 64 + j * 8 + (lane & 3) * 2;
            float v0 = sv[nc], v1 = sv[nc + 1];
            s0 = fmaf(fast_tanh(acc[mt][j][0] + sdec[b0 * CTAN + nc]), v0, s0);
            s0 = fmaf(fast_tanh(acc[mt][j][1] + sdec[b0 * CTAN + nc + 1]), v1, s0);
            s1 = fmaf(fast_tanh(acc[mt][j][2] + sdec[b1 * CTAN + nc]), v0, s1);
            s1 = fmaf(fast_tanh(acc[mt][j][3] + sdec[b1 * CTAN + nc + 1]), v1, s1);
        }
        s0 += __shfl_xor_sync(0xffffffffu, s0, 1);
        s0 += __shfl_xor_sync(0xffffffffu, s0, 2);
        s1 += __shfl_xor_sync(0xffffffffu, s1, 1);
        s1 += __shfl_xor_sync(0xffffffffu, s1, 2);
        if ((lane & 3) == 0) {
            size_t m0 = m_base + rowA;
            size_t m1 = m0 + 8;
            atomicAdd(&g_scores[(m0 & 31) * S_ + (m0 >> 5)], s0);
            atomicAdd(&g_scores[(m1 & 31) * S_ + (m1 >> 5)], s1);
        }
    }
}

// ---------------------------------------------------------------------------
// 4. softmax over S per batch
// ---------------------------------------------------------------------------
__global__ __launch_bounds__(256)
void softmax_kernel(float* __restrict__ wout) {
    int b = blockIdx.x;
    int tid = threadIdx.x;
    __shared__ float sm[256];

    float vals[8];
    float mx = -1e30f;
#pragma unroll
    for (int i = 0; i < 8; i++) {
        vals[i] = g_scores[b * S_ + tid + i * 256];
        mx = fmaxf(mx, vals[i]);
    }
    sm[tid] = mx; __syncthreads();
    for (int o = 128; o; o >>= 1) {
        if (tid < o) sm[tid] = fmaxf(sm[tid], sm[tid + o]);
        __syncthreads();
    }
    mx = sm[0]; __syncthreads();

    float sum = 0.f;
#pragma unroll
    for (int i = 0; i < 8; i++) { vals[i] = expf(vals[i] - mx); sum += vals[i]; }
    sm[tid] = sum; __syncthreads();
    for (int o = 128; o; o >>= 1) {
        if (tid < o) sm[tid] += sm[tid + o];
        __syncthreads();
    }
    float inv = 1.f / sm[0];
#pragma unroll
    for (int i = 0; i < 8; i++) wout[b * S_ + tid + i * 256] = vals[i] * inv;
}

// ---------------------------------------------------------------------------
// 5. context[b,e] = sum_s w[b,s] * enc[s,b,e]
// ---------------------------------------------------------------------------
#define CSPLIT 8
__global__ __launch_bounds__(256)
void context_kernel(const float* __restrict__ enc, const float* __restrict__ w,
                    float* __restrict__ ctx) {
    int e = blockIdx.x * 256 + threadIdx.x;
    int b = blockIdx.y;
    int s0 = blockIdx.z * (S_ / CSPLIT);
    const float* base = enc + (size_t)b * E_ + e;
    float acc0 = 0.f, acc1 = 0.f, acc2 = 0.f, acc3 = 0.f;
#pragma unroll 2
    for (int s = s0; s < s0 + S_ / CSPLIT; s += 4) {
        acc0 += w[b * S_ + s + 0] * base[(size_t)(s + 0) * (B_ * E_)];
        acc1 += w[b * S_ + s + 1] * base[(size_t)(s + 1) * (B_ * E_)];
        acc2 += w[b * S_ + s + 2] * base[(size_t)(s + 2) * (B_ * E_)];
        acc3 += w[b * S_ + s + 3] * base[(size_t)(s + 3) * (B_ * E_)];
    }
    atomicAdd(&ctx[b * E_ + e], (acc0 + acc1) + (acc2 + acc3));
}

// ---------------------------------------------------------------------------
extern "C" void kernel_launch(void* const* d_in, const int* in_sizes, int n_in,
                              void* d_out, int out_size) {
    const float* hidden = (const float*)d_in[0];  // [B,D]
    const float* enc    = (const float*)d_in[1];  // [S,B,E]
    const float* We     = (const float*)d_in[2];  // [D,E]
    const float* Wd     = (const float*)d_in[3];  // [D,D]
    const float* v      = (const float*)d_in[4];  // [D]
    float* out = (float*)d_out;                   // [B*E context | B*S weights]
    float* wout = out + B_ * E_;

    cudaFuncSetAttribute(score_mma_kernel,
                         cudaFuncAttributeMaxDynamicSharedMemorySize, SMEM_BYTES);

    __half *ah, *bh;
    cudaGetSymbolAddress((void**)&ah, g_ah);
    cudaGetSymbolAddress((void**)&bh, g_bh);

    init_kernel<<<(B_ * S_ + 255) / 256, 256>>>(out);
    cvt_h_kernel<<<(size_t)M_ * K_ / 2048, 256>>>(enc, ah);
    cvt_h_kernel<<<(size_t)D_ * K_ / 2048, 256>>>(We, bh);
    dec_proj_kernel<<<(B_ * D_ * 32 + 255) / 256, 256>>>(hidden, Wd);
    score_mma_kernel<<<dim3(NT, MT), 256, SMEM_BYTES>>>(v);
    softmax_kernel<<<B_, 256>>>(wout);
    context_kernel<<<dim3(E_ / 256, B_, CSPLIT), 256>>>(enc, wout, out);
}

// round 8
// speedup vs baseline: 5.4208x; 1.2767x over previous
#include <cuda_runtime.h>
#include <cuda_fp16.h>
#include <math.h>
#include <stdint.h>

#define B_ 32
#define S_ 2048
#define E_ 1024
#define D_ 1024
#define K_ 1024
#define M_ (S_ * B_)   // 65536

// GEMM tiling
#define CTAM 128
#define CTAN 128
#define CKS 64                 // K per chunk
#define NCHUNK (K_ / CKS)      // 16
#define NT (D_ / CTAN)         // 8
#define MT (M_ / CTAM)         // 512

// SMEM per stage: 2 tiles of 128 rows x 128B = 16KB each
#define OFF_AH 0
#define OFF_BH 16384
#define STAGE_BYTES 32768
#define NSTAGE 3
#define SMEM_BYTES (NSTAGE * STAGE_BYTES)   // 96KB dynamic

__device__ float g_scores[B_ * S_];
__device__ float g_dec[B_ * D_];
__device__ __half g_ah[(size_t)M_ * K_];   // fp16(A)
__device__ __half g_bh[(size_t)D_ * K_];   // fp16(B)

// ---------------------------------------------------------------------------
__device__ __forceinline__ uint32_t smem_u32(const void* p) {
    uint32_t a;
    asm("{ .reg .u64 t; cvta.to.shared.u64 t, %1; cvt.u32.u64 %0, t; }" : "=r"(a) : "l"(p));
    return a;
}

// swizzled offset within a 128-row x 128B tile (8 16B-groups/row, 8-way XOR)
__device__ __forceinline__ uint32_t sw128(uint32_t row, uint32_t g) {
    return (row << 7) | (((g ^ row) & 7u) << 4);
}

__device__ __forceinline__ void ldsm4(uint32_t* r, uint32_t addr) {
    asm volatile("ldmatrix.sync.aligned.m8n8.x4.shared.b16 {%0,%1,%2,%3}, [%4];"
                 : "=r"(r[0]), "=r"(r[1]), "=r"(r[2]), "=r"(r[3]) : "r"(addr));
}

__device__ __forceinline__ void mma_f16(float* d, const uint32_t* a, const uint32_t* b) {
    asm volatile(
        "mma.sync.aligned.m16n8k16.row.col.f32.f16.f16.f32 "
        "{%0,%1,%2,%3}, {%4,%5,%6,%7}, {%8,%9}, {%0,%1,%2,%3};"
        : "+f"(d[0]), "+f"(d[1]), "+f"(d[2]), "+f"(d[3])
        : "r"(a[0]), "r"(a[1]), "r"(a[2]), "r"(a[3]), "r"(b[0]), "r"(b[1]));
}

#define CPA16(dst, src) \
    asm volatile("cp.async.cg.shared.global [%0], [%1], 16;" :: "r"(dst), "l"(src))

// tanh via rational approx (FMA-only, no MUFU in the hot path)
__device__ __forceinline__ float fast_tanh(float x) {
    float cx = fminf(fmaxf(x, -7.90531110763549805f), 7.90531110763549805f);
    float x2 = cx * cx;
    float p = fmaf(x2, -2.76076847742355e-16f, 2.00018790482477e-13f);
    p = fmaf(p, x2, -8.60467152213735e-11f);
    p = fmaf(p, x2, 5.12229709037114e-08f);
    p = fmaf(p, x2, 1.48572235717979e-05f);
    p = fmaf(p, x2, 6.37261928875436e-04f);
    p = fmaf(p, x2, 4.89352455891786e-03f);
    p = p * cx;
    float q = fmaf(x2, 1.19825839466702e-06f, 1.18534705686654e-04f);
    q = fmaf(q, x2, 2.26843463243900e-03f);
    q = fmaf(q, x2, 4.89352518554385e-03f);
    float r = __uint_as_float(0x7EF127EAu - __float_as_uint(q));
    r = r * (2.0f - q * r);
    r = r * (2.0f - q * r);
    r = r * (2.0f - q * r);
    return p * r;
}

// ---------------------------------------------------------------------------
// 0. init
// ---------------------------------------------------------------------------
__global__ void init_kernel(float* __restrict__ out) {
    int i = blockIdx.x * blockDim.x + threadIdx.x;
    if (i < B_ * S_) g_scores[i] = 0.f;
    if (i < B_ * E_) out[i] = 0.f;
}

// ---------------------------------------------------------------------------
// 1. convert fp32 -> fp16 (8 elems/thread)
// ---------------------------------------------------------------------------
__global__ __launch_bounds__(256)
void cvt_h_kernel(const float* __restrict__ src, __half* __restrict__ dst) {
    size_t idx = ((size_t)blockIdx.x * 256 + threadIdx.x) * 8;
    const float4* s4 = (const float4*)(src + idx);
    float4 f0 = s4[0], f1 = s4[1];
    __half2 h[4];
    h[0] = __floats2half2_rn(f0.x, f0.y);
    h[1] = __floats2half2_rn(f0.z, f0.w);
    h[2] = __floats2half2_rn(f1.x, f1.y);
    h[3] = __floats2half2_rn(f1.z, f1.w);
    *(uint4*)(dst + idx) = *(uint4*)h;
}

// ---------------------------------------------------------------------------
// 2. dec_proj[b*D+d] = sum_k hidden[b,k] * Wd[d,k]
// ---------------------------------------------------------------------------
__global__ __launch_bounds__(256)
void dec_proj_kernel(const float* __restrict__ hidden, const float* __restrict__ Wd) {
    int warp = (blockIdx.x * blockDim.x + threadIdx.x) >> 5;
    int lane = threadIdx.x & 31;
    if (warp >= B_ * D_) return;
    int b = warp >> 10;
    int d = warp & (D_ - 1);
    const float4* h4 = (const float4*)(hidden + (size_t)b * D_);
    const float4* w4 = (const float4*)(Wd + (size_t)d * D_);
    float s = 0.f;
#pragma unroll
    for (int k = lane; k < D_ / 4; k += 32) {
        float4 a = h4[k], w = w4[k];
        s += a.x * w.x + a.y * w.y + a.z * w.z + a.w * w.w;
    }
#pragma unroll
    for (int o = 16; o; o >>= 1) s += __shfl_down_sync(0xffffffffu, s, o);
    if (!lane) g_dec[warp] = s;
}

// ---------------------------------------------------------------------------
// 3. Fused scores GEMM: fp16, 3-stage cp.async ring, 1 barrier per chunk
// ---------------------------------------------------------------------------
__global__ __launch_bounds__(256, 2)
void score_mma_kernel(const float* __restrict__ v) {
    extern __shared__ __align__(1024) char smem[];
    const uint32_t sb = smem_u32(smem);

    const int tid = threadIdx.x;
    const int wid = tid >> 5;
    const int lane = tid & 31;
    const int wm = wid >> 1;          // 0..3
    const int wn = wid & 1;           // 0..1
    const int n_base = blockIdx.x * CTAN;
    const size_t m_base = (size_t)blockIdx.y * CTAM;

    // per-thread copy task: row lr (0..127), half lh -> 4 16B groups per tile
    const int lr = tid >> 1;
    const int lh = tid & 1;
    const __half* Ah_r = g_ah + (m_base + lr) * (size_t)K_;
    const __half* Bh_r = g_bh + (size_t)(n_base + lr) * K_;
    uint32_t so[4];
#pragma unroll
    for (int i = 0; i < 4; i++) so[i] = sw128(lr, lh * 4 + i);

#define PREFETCH(c, st)                                                       \
    {                                                                         \
        uint32_t stb_ = sb + (st) * STAGE_BYTES;                              \
        int ko_ = (c) * CKS;                                                  \
        _Pragma("unroll")                                                     \
        for (int i_ = 0; i_ < 4; i_++) {                                      \
            int ge_ = ko_ + (lh * 4 + i_) * 8;                                \
            CPA16(stb_ + OFF_AH + so[i_], Ah_r + ge_);                        \
            CPA16(stb_ + OFF_BH + so[i_], Bh_r + ge_);                        \
        }                                                                     \
    }

    float acc[2][8][4];
#pragma unroll
    for (int mt = 0; mt < 2; mt++)
#pragma unroll
        for (int j = 0; j < 8; j++)
#pragma unroll
            for (int cc = 0; cc < 4; cc++) acc[mt][j][cc] = 0.f;

    // ldmatrix per-lane address components
    const uint32_t a_row = wm * 32 + (lane & 15);
    const uint32_t a_kg = (uint32_t)(lane >> 4);
    const uint32_t b_row_lo = wn * 64 + (lane & 7) + ((lane & 16) ? 8 : 0);
    const uint32_t b_kg = (uint32_t)((lane >> 3) & 1);

    PREFETCH(0, 0);
    asm volatile("cp.async.commit_group;" ::: "memory");
    PREFETCH(1, 1);
    asm volatile("cp.async.commit_group;" ::: "memory");

    int st = 0, stp = 2;
    for (int c = 0; c < NCHUNK; c++) {
        asm volatile("cp.async.wait_group 1;" ::: "memory");
        __syncthreads();   // stage st data ready; all warps done reading stage stp

        const uint32_t stb = sb + st * STAGE_BYTES;
#pragma unroll
        for (int ks = 0; ks < 4; ks++) {
            uint32_t ah[2][4];
#pragma unroll
            for (int mt = 0; mt < 2; mt++) {
                uint32_t off = sw128(a_row + mt * 16, 2 * ks + a_kg);
                ldsm4(ah[mt], stb + OFF_AH + off);
            }
#pragma unroll
            for (int half = 0; half < 2; half++) {
                uint32_t bh[4][2];
#pragma unroll
                for (int j2 = 0; j2 < 2; j2++) {
                    uint32_t off = sw128(b_row_lo + (half * 2 + j2) * 16, 2 * ks + b_kg);
                    uint32_t t[4];
                    ldsm4(t, stb + OFF_BH + off);
                    bh[j2 * 2][0] = t[0]; bh[j2 * 2][1] = t[1];
                    bh[j2 * 2 + 1][0] = t[2]; bh[j2 * 2 + 1][1] = t[3];
                }
#pragma unroll
                for (int mt = 0; mt < 2; mt++)
#pragma unroll
                    for (int j = 0; j < 4; j++)
                        mma_f16(acc[mt][half * 4 + j], ah[mt], bh[j]);
            }
        }
        if (c + 2 < NCHUNK) PREFETCH(c + 2, stp);
        asm volatile("cp.async.commit_group;" ::: "memory");
        st = (st == 2) ? 0 : st + 1;
        stp = (stp == 2) ? 0 : stp + 1;
    }
    asm volatile("cp.async.wait_group 0;" ::: "memory");
    __syncthreads();

    // ---- epilogue: stage dec tile + v into smem, tanh + v-dot, reduce ----
    float* sdec = (float*)smem;            // [32][128] = 16KB
    float* sv = (float*)(smem + 16384);    // [128]
    for (int i = tid; i < B_ * CTAN; i += 256) {
        int b = i >> 7, n = i & (CTAN - 1);
        sdec[b * CTAN + n] = g_dec[b * D_ + n_base + n];
    }
    if (tid < CTAN) sv[tid] = v[n_base + tid];
    __syncthreads();

#pragma unroll
    for (int mt = 0; mt < 2; mt++) {
        int rowA = wm * 32 + mt * 16 + (lane >> 2);
        int b0 = rowA & 31, b1 = (rowA + 8) & 31;
        float s0 = 0.f, s1 = 0.f;
#pragma unroll
        for (int j = 0; j < 8; j++) {
            int nc = wn * 64 + j * 8 + (lane & 3) * 2;
            float v0 = sv[nc], v1 = sv[nc + 1];
            s0 = fmaf(fast_tanh(acc[mt][j][0] + sdec[b0 * CTAN + nc]), v0, s0);
            s0 = fmaf(fast_tanh(acc[mt][j][1] + sdec[b0 * CTAN + nc + 1]), v1, s0);
            s1 = fmaf(fast_tanh(acc[mt][j][2] + sdec[b1 * CTAN + nc]), v0, s1);
            s1 = fmaf(fast_tanh(acc[mt][j][3] + sdec[b1 * CTAN + nc + 1]), v1, s1);
        }
        s0 += __shfl_xor_sync(0xffffffffu, s0, 1);
        s0 += __shfl_xor_sync(0xffffffffu, s0, 2);
        s1 += __shfl_xor_sync(0xffffffffu, s1, 1);
        s1 += __shfl_xor_sync(0xffffffffu, s1, 2);
        if ((lane & 3) == 0) {
            size_t m0 = m_base + rowA;
            size_t m1 = m0 + 8;
            atomicAdd(&g_scores[(m0 & 31) * S_ + (m0 >> 5)], s0);
            atomicAdd(&g_scores[(m1 & 31) * S_ + (m1 >> 5)], s1);
        }
    }
}

// ---------------------------------------------------------------------------
// 4. softmax over S per batch
// ---------------------------------------------------------------------------
__global__ __launch_bounds__(256)
void softmax_kernel(float* __restrict__ wout) {
    int b = blockIdx.x;
    int tid = threadIdx.x;
    __shared__ float sm[256];

    float vals[8];
    float mx = -1e30f;
#pragma unroll
    for (int i = 0; i < 8; i++) {
        vals[i] = g_scores[b * S_ + tid + i * 256];
        mx = fmaxf(mx, vals[i]);
    }
    sm[tid] = mx; __syncthreads();
    for (int o = 128; o; o >>= 1) {
        if (tid < o) sm[tid] = fmaxf(sm[tid], sm[tid + o]);
        __syncthreads();
    }
    mx = sm[0]; __syncthreads();

    float sum = 0.f;
#pragma unroll
    for (int i = 0; i < 8; i++) { vals[i] = expf(vals[i] - mx); sum += vals[i]; }
    sm[tid] = sum; __syncthreads();
    for (int o = 128; o; o >>= 1) {
        if (tid < o) sm[tid] += sm[tid + o];
        __syncthreads();
    }
    float inv = 1.f / sm[0];
#pragma unroll
    for (int i = 0; i < 8; i++) wout[b * S_ + tid + i * 256] = vals[i] * inv;
}

// ---------------------------------------------------------------------------
// 5. context[b,e] = sum_s w[b,s] * enc[s,b,e]
// ---------------------------------------------------------------------------
#define CSPLIT 8
__global__ __launch_bounds__(256)
void context_kernel(const float* __restrict__ enc, const float* __restrict__ w,
                    float* __restrict__ ctx) {
    int e = blockIdx.x * 256 + threadIdx.x;
    int b = blockIdx.y;
    int s0 = blockIdx.z * (S_ / CSPLIT);
    const float* base = enc + (size_t)b * E_ + e;
    float acc0 = 0.f, acc1 = 0.f, acc2 = 0.f, acc3 = 0.f;
#pragma unroll 2
    for (int s = s0; s < s0 + S_ / CSPLIT; s += 4) {
        acc0 += w[b * S_ + s + 0] * base[(size_t)(s + 0) * (B_ * E_)];
        acc1 += w[b * S_ + s + 1] * base[(size_t)(s + 1) * (B_ * E_)];
        acc2 += w[b * S_ + s + 2] * base[(size_t)(s + 2) * (B_ * E_)];
        acc3 += w[b * S_ + s + 3] * base[(size_t)(s + 3) * (B_ * E_)];
    }
    atomicAdd(&ctx[b * E_ + e], (acc0 + acc1) + (acc2 + acc3));
}

// ---------------------------------------------------------------------------
extern "C" void kernel_launch(void* const* d_in, const int* in_sizes, int n_in,
                              void* d_out, int out_size) {
    const float* hidden = (const float*)d_in[0];  // [B,D]
    const float* enc    = (const float*)d_in[1];  // [S,B,E]
    const float* We     = (const float*)d_in[2];  // [D,E]
    const float* Wd     = (const float*)d_in[3];  // [D,D]
    const float* v      = (const float*)d_in[4];  // [D]
    float* out = (float*)d_out;                   // [B*E context | B*S weights]
    float* wout = out + B_ * E_;

    cudaFuncSetAttribute(score_mma_kernel,
                         cudaFuncAttributeMaxDynamicSharedMemorySize, SMEM_BYTES);

    __half *ah, *bh;
    cudaGetSymbolAddress((void**)&ah, g_ah);
    cudaGetSymbolAddress((void**)&bh, g_bh);

    init_kernel<<<(B_ * S_ + 255) / 256, 256>>>(out);
    cvt_h_kernel<<<(size_t)M_ * K_ / 2048, 256>>>(enc, ah);
    cvt_h_kernel<<<(size_t)D_ * K_ / 2048, 256>>>(We, bh);
    dec_proj_kernel<<<(B_ * D_ * 32 + 255) / 256, 256>>>(hidden, Wd);
    score_mma_kernel<<<dim3(NT, MT), 256, SMEM_BYTES>>>(v);
    softmax_kernel<<<B_, 256>>>(wout);
    context_kernel<<<dim3(E_ / 256, B_, CSPLIT), 256>>>(enc, wout, out);
}

// round 9
// speedup vs baseline: 5.4634x; 1.0079x over previous
#include <cuda_runtime.h>
#include <cuda_fp16.h>
#include <math.h>
#include <stdint.h>

#define B_ 32
#define S_ 2048
#define E_ 1024
#define D_ 1024
#define K_ 1024
#define M_ (S_ * B_)   // 65536

// GEMM tiling
#define CTAM 128
#define CTAN 128
#define CKS 64                 // K per chunk
#define NCHUNK (K_ / CKS)      // 16
#define NT (D_ / CTAN)         // 8
#define MT (M_ / CTAM)         // 512

// SMEM per stage: 2 tiles of 128 rows x 128B = 16KB each
#define OFF_AH 0
#define OFF_BH 16384
#define STAGE_BYTES 32768
#define NSTAGE 3
#define SMEM_BYTES (NSTAGE * STAGE_BYTES)   // 96KB dynamic

__device__ float g_scores[B_ * S_];
__device__ float g_dec[B_ * D_];
__device__ __half g_ah[(size_t)M_ * K_];   // fp16(A)
__device__ __half g_bh[(size_t)D_ * K_];   // fp16(B)

// ---------------------------------------------------------------------------
__device__ __forceinline__ uint32_t smem_u32(const void* p) {
    uint32_t a;
    asm("{ .reg .u64 t; cvta.to.shared.u64 t, %1; cvt.u32.u64 %0, t; }" : "=r"(a) : "l"(p));
    return a;
}

// swizzled offset within a 128-row x 128B tile (8 16B-groups/row, 8-way XOR)
__device__ __forceinline__ uint32_t sw128(uint32_t row, uint32_t g) {
    return (row << 7) | (((g ^ row) & 7u) << 4);
}

__device__ __forceinline__ void ldsm4(uint32_t* r, uint32_t addr) {
    asm volatile("ldmatrix.sync.aligned.m8n8.x4.shared.b16 {%0,%1,%2,%3}, [%4];"
                 : "=r"(r[0]), "=r"(r[1]), "=r"(r[2]), "=r"(r[3]) : "r"(addr));
}

__device__ __forceinline__ void mma_f16(float* d, const uint32_t* a, const uint32_t* b) {
    asm volatile(
        "mma.sync.aligned.m16n8k16.row.col.f32.f16.f16.f32 "
        "{%0,%1,%2,%3}, {%4,%5,%6,%7}, {%8,%9}, {%0,%1,%2,%3};"
        : "+f"(d[0]), "+f"(d[1]), "+f"(d[2]), "+f"(d[3])
        : "r"(a[0]), "r"(a[1]), "r"(a[2]), "r"(a[3]), "r"(b[0]), "r"(b[1]));
}

#define CPA16(dst, src) \
    asm volatile("cp.async.cg.shared.global [%0], [%1], 16;" :: "r"(dst), "l"(src))

// tanh via rational approx (FMA-only, no MUFU in the hot path)
__device__ __forceinline__ float fast_tanh(float x) {
    float cx = fminf(fmaxf(x, -7.90531110763549805f), 7.90531110763549805f);
    float x2 = cx * cx;
    float p = fmaf(x2, -2.76076847742355e-16f, 2.00018790482477e-13f);
    p = fmaf(p, x2, -8.60467152213735e-11f);
    p = fmaf(p, x2, 5.12229709037114e-08f);
    p = fmaf(p, x2, 1.48572235717979e-05f);
    p = fmaf(p, x2, 6.37261928875436e-04f);
    p = fmaf(p, x2, 4.89352455891786e-03f);
    p = p * cx;
    float q = fmaf(x2, 1.19825839466702e-06f, 1.18534705686654e-04f);
    q = fmaf(q, x2, 2.26843463243900e-03f);
    q = fmaf(q, x2, 4.89352518554385e-03f);
    float r = __uint_as_float(0x7EF127EAu - __float_as_uint(q));
    r = r * (2.0f - q * r);
    r = r * (2.0f - q * r);
    r = r * (2.0f - q * r);
    return p * r;
}

// ---------------------------------------------------------------------------
// 0. init
// ---------------------------------------------------------------------------
__global__ void init_kernel(float* __restrict__ out) {
    int i = blockIdx.x * blockDim.x + threadIdx.x;
    if (i < B_ * S_) g_scores[i] = 0.f;
    if (i < B_ * E_) out[i] = 0.f;
}

// ---------------------------------------------------------------------------
// 1. convert fp32 -> fp16 (8 elems/thread)
// ---------------------------------------------------------------------------
__global__ __launch_bounds__(256)
void cvt_h_kernel(const float* __restrict__ src, __half* __restrict__ dst) {
    size_t idx = ((size_t)blockIdx.x * 256 + threadIdx.x) * 8;
    const float4* s4 = (const float4*)(src + idx);
    float4 f0 = s4[0], f1 = s4[1];
    __half2 h[4];
    h[0] = __floats2half2_rn(f0.x, f0.y);
    h[1] = __floats2half2_rn(f0.z, f0.w);
    h[2] = __floats2half2_rn(f1.x, f1.y);
    h[3] = __floats2half2_rn(f1.z, f1.w);
    *(uint4*)(dst + idx) = *(uint4*)h;
}

// ---------------------------------------------------------------------------
// 2. dec_proj: warp computes 4 outputs (d..d+3) for one b, hidden in regs
// ---------------------------------------------------------------------------
__global__ __launch_bounds__(256)
void dec_proj_kernel(const float* __restrict__ hidden, const float* __restrict__ Wd) {
    int warp = (blockIdx.x * blockDim.x + threadIdx.x) >> 5;
    int lane = threadIdx.x & 31;
    if (warp >= B_ * (D_ / 4)) return;
    int b = warp >> 8;               // / (D_/4)
    int dg = (warp & 255) << 2;
    const float4* h4 = (const float4*)(hidden + (size_t)b * D_);
    float4 ha[8];
#pragma unroll
    for (int i = 0; i < 8; i++) ha[i] = h4[lane + 32 * i];
    float s[4];
#pragma unroll
    for (int j = 0; j < 4; j++) {
        const float4* w4 = (const float4*)(Wd + (size_t)(dg + j) * D_);
        float acc = 0.f;
#pragma unroll
        for (int i = 0; i < 8; i++) {
            float4 w = w4[lane + 32 * i];
            acc += ha[i].x * w.x + ha[i].y * w.y + ha[i].z * w.z + ha[i].w * w.w;
        }
        s[j] = acc;
    }
#pragma unroll
    for (int j = 0; j < 4; j++)
#pragma unroll
        for (int o = 16; o; o >>= 1) s[j] += __shfl_down_sync(0xffffffffu, s[j], o);
    if (lane == 0)
        *(float4*)(g_dec + (size_t)b * D_ + dg) = make_float4(s[0], s[1], s[2], s[3]);
}

// ---------------------------------------------------------------------------
// 3. Fused scores GEMM: fp16, 3-stage cp.async ring, early prefetch
// ---------------------------------------------------------------------------
__global__ __launch_bounds__(256, 2)
void score_mma_kernel(const float* __restrict__ v) {
    extern __shared__ __align__(1024) char smem[];
    const uint32_t sb = smem_u32(smem);

    const int tid = threadIdx.x;
    const int wid = tid >> 5;
    const int lane = tid & 31;
    const int wm = wid >> 1;          // 0..3
    const int wn = wid & 1;           // 0..1
    const int n_base = blockIdx.x * CTAN;
    const size_t m_base = (size_t)blockIdx.y * CTAM;

    // per-thread copy task: row lr (0..127), half lh -> 4 16B groups per tile
    const int lr = tid >> 1;
    const int lh = tid & 1;
    const __half* Ah_r = g_ah + (m_base + lr) * (size_t)K_;
    const __half* Bh_r = g_bh + (size_t)(n_base + lr) * K_;
    uint32_t so[4];
#pragma unroll
    for (int i = 0; i < 4; i++) so[i] = sw128(lr, lh * 4 + i);

#define PREFETCH(c, st)                                                       \
    {                                                                         \
        uint32_t stb_ = sb + (st) * STAGE_BYTES;                              \
        int ko_ = (c) * CKS;                                                  \
        _Pragma("unroll")                                                     \
        for (int i_ = 0; i_ < 4; i_++) {                                      \
            int ge_ = ko_ + (lh * 4 + i_) * 8;                                \
            CPA16(stb_ + OFF_AH + so[i_], Ah_r + ge_);                        \
            CPA16(stb_ + OFF_BH + so[i_], Bh_r + ge_);                        \
        }                                                                     \
    }

    float acc[2][8][4];
#pragma unroll
    for (int mt = 0; mt < 2; mt++)
#pragma unroll
        for (int j = 0; j < 8; j++)
#pragma unroll
            for (int cc = 0; cc < 4; cc++) acc[mt][j][cc] = 0.f;

    // ldmatrix per-lane address components
    const uint32_t a_row = wm * 32 + (lane & 15);
    const uint32_t a_kg = (uint32_t)(lane >> 4);
    const uint32_t b_row_lo = wn * 64 + (lane & 7) + ((lane & 16) ? 8 : 0);
    const uint32_t b_kg = (uint32_t)((lane >> 3) & 1);

    PREFETCH(0, 0);
    asm volatile("cp.async.commit_group;" ::: "memory");
    PREFETCH(1, 1);
    asm volatile("cp.async.commit_group;" ::: "memory");

    int st = 0, stp = 2;
    for (int c = 0; c < NCHUNK; c++) {
        asm volatile("cp.async.wait_group 1;" ::: "memory");
        __syncthreads();   // stage st ready; all warps done reading stage stp

        // early prefetch for chunk c+2 into the just-freed stage stp
        if (c + 2 < NCHUNK) PREFETCH(c + 2, stp);
        asm volatile("cp.async.commit_group;" ::: "memory");

        const uint32_t stb = sb + st * STAGE_BYTES;
#pragma unroll
        for (int ks = 0; ks < 4; ks++) {
            uint32_t ah[2][4];
#pragma unroll
            for (int mt = 0; mt < 2; mt++) {
                uint32_t off = sw128(a_row + mt * 16, 2 * ks + a_kg);
                ldsm4(ah[mt], stb + OFF_AH + off);
            }
#pragma unroll
            for (int half = 0; half < 2; half++) {
                uint32_t bh[4][2];
#pragma unroll
                for (int j2 = 0; j2 < 2; j2++) {
                    uint32_t off = sw128(b_row_lo + (half * 2 + j2) * 16, 2 * ks + b_kg);
                    uint32_t t[4];
                    ldsm4(t, stb + OFF_BH + off);
                    bh[j2 * 2][0] = t[0]; bh[j2 * 2][1] = t[1];
                    bh[j2 * 2 + 1][0] = t[2]; bh[j2 * 2 + 1][1] = t[3];
                }
#pragma unroll
                for (int mt = 0; mt < 2; mt++)
#pragma unroll
                    for (int j = 0; j < 4; j++)
                        mma_f16(acc[mt][half * 4 + j], ah[mt], bh[j]);
            }
        }
        st = (st == 2) ? 0 : st + 1;
        stp = (stp == 2) ? 0 : stp + 1;
    }
    asm volatile("cp.async.wait_group 0;" ::: "memory");
    __syncthreads();

    // ---- epilogue: stage dec tile + v into smem, tanh + v-dot, reduce ----
    float* sdec = (float*)smem;            // [32][128] = 16KB
    float* sv = (float*)(smem + 16384);    // [128]
    for (int i = tid; i < B_ * CTAN; i += 256) {
        int b = i >> 7, n = i & (CTAN - 1);
        sdec[b * CTAN + n] = g_dec[b * D_ + n_base + n];
    }
    if (tid < CTAN) sv[tid] = v[n_base + tid];
    __syncthreads();

#pragma unroll
    for (int mt = 0; mt < 2; mt++) {
        int rowA = wm * 32 + mt * 16 + (lane >> 2);
        int b0 = rowA & 31, b1 = (rowA + 8) & 31;
        float s0 = 0.f, s1 = 0.f;
#pragma unroll
        for (int j = 0; j < 8; j++) {
            int nc = wn * 64 + j * 8 + (lane & 3) * 2;
            float v0 = sv[nc], v1 = sv[nc + 1];
            s0 = fmaf(fast_tanh(acc[mt][j][0] + sdec[b0 * CTAN + nc]), v0, s0);
            s0 = fmaf(fast_tanh(acc[mt][j][1] + sdec[b0 * CTAN + nc + 1]), v1, s0);
            s1 = fmaf(fast_tanh(acc[mt][j][2] + sdec[b1 * CTAN + nc]), v0, s1);
            s1 = fmaf(fast_tanh(acc[mt][j][3] + sdec[b1 * CTAN + nc + 1]), v1, s1);
        }
        s0 += __shfl_xor_sync(0xffffffffu, s0, 1);
        s0 += __shfl_xor_sync(0xffffffffu, s0, 2);
        s1 += __shfl_xor_sync(0xffffffffu, s1, 1);
        s1 += __shfl_xor_sync(0xffffffffu, s1, 2);
        if ((lane & 3) == 0) {
            size_t m0 = m_base + rowA;
            size_t m1 = m0 + 8;
            atomicAdd(&g_scores[(m0 & 31) * S_ + (m0 >> 5)], s0);
            atomicAdd(&g_scores[(m1 & 31) * S_ + (m1 >> 5)], s1);
        }
    }
}

// ---------------------------------------------------------------------------
// 4. softmax over S per batch
// ---------------------------------------------------------------------------
__global__ __launch_bounds__(256)
void softmax_kernel(float* __restrict__ wout) {
    int b = blockIdx.x;
    int tid = threadIdx.x;
    __shared__ float sm[256];

    float vals[8];
    float mx = -1e30f;
#pragma unroll
    for (int i = 0; i < 8; i++) {
        vals[i] = g_scores[b * S_ + tid + i * 256];
        mx = fmaxf(mx, vals[i]);
    }
    sm[tid] = mx; __syncthreads();
    for (int o = 128; o; o >>= 1) {
        if (tid < o) sm[tid] = fmaxf(sm[tid], sm[tid + o]);
        __syncthreads();
    }
    mx = sm[0]; __syncthreads();

    float sum = 0.f;
#pragma unroll
    for (int i = 0; i < 8; i++) { vals[i] = expf(vals[i] - mx); sum += vals[i]; }
    sm[tid] = sum; __syncthreads();
    for (int o = 128; o; o >>= 1) {
        if (tid < o) sm[tid] += sm[tid + o];
        __syncthreads();
    }
    float inv = 1.f / sm[0];
#pragma unroll
    for (int i = 0; i < 8; i++) wout[b * S_ + tid + i * 256] = vals[i] * inv;
}

// ---------------------------------------------------------------------------
// 5. context[b,e] = sum_s w[b,s] * enc_fp16[s,b,e]  (reads g_ah, half2)
// ---------------------------------------------------------------------------
#define CSPLIT 8
__global__ __launch_bounds__(256)
void context_kernel(const float* __restrict__ w, float* __restrict__ ctx) {
    int e2 = blockIdx.x * 256 + threadIdx.x;   // half2 index, 0..511
    int b = blockIdx.y;
    int s0 = blockIdx.z * (S_ / CSPLIT);
    const __half2* base = (const __half2*)g_ah + (size_t)b * (K_ / 2) + e2;
    const size_t str = (size_t)B_ * (K_ / 2);
    float ax0 = 0.f, ay0 = 0.f, ax1 = 0.f, ay1 = 0.f;
    float ax2 = 0.f, ay2 = 0.f, ax3 = 0.f, ay3 = 0.f;
#pragma unroll 2
    for (int s = s0; s < s0 + S_ / CSPLIT; s += 4) {
        float w0 = w[b * S_ + s + 0], w1 = w[b * S_ + s + 1];
        float w2 = w[b * S_ + s + 2], w3 = w[b * S_ + s + 3];
        float2 f0 = __half22float2(base[(size_t)(s + 0) * str]);
        float2 f1 = __half22float2(base[(size_t)(s + 1) * str]);
        float2 f2 = __half22float2(base[(size_t)(s + 2) * str]);
        float2 f3 = __half22float2(base[(size_t)(s + 3) * str]);
        ax0 = fmaf(w0, f0.x, ax0); ay0 = fmaf(w0, f0.y, ay0);
        ax1 = fmaf(w1, f1.x, ax1); ay1 = fmaf(w1, f1.y, ay1);
        ax2 = fmaf(w2, f2.x, ax2); ay2 = fmaf(w2, f2.y, ay2);
        ax3 = fmaf(w3, f3.x, ax3); ay3 = fmaf(w3, f3.y, ay3);
    }
    atomicAdd(&ctx[b * E_ + 2 * e2], (ax0 + ax1) + (ax2 + ax3));
    atomicAdd(&ctx[b * E_ + 2 * e2 + 1], (ay0 + ay1) + (ay2 + ay3));
}

// ---------------------------------------------------------------------------
extern "C" void kernel_launch(void* const* d_in, const int* in_sizes, int n_in,
                              void* d_out, int out_size) {
    const float* hidden = (const float*)d_in[0];  // [B,D]
    const float* enc    = (const float*)d_in[1];  // [S,B,E]
    const float* We     = (const float*)d_in[2];  // [D,E]
    const float* Wd     = (const float*)d_in[3];  // [D,D]
    const float* v      = (const float*)d_in[4];  // [D]
    float* out = (float*)d_out;                   // [B*E context | B*S weights]
    float* wout = out + B_ * E_;

    cudaFuncSetAttribute(score_mma_kernel,
                         cudaFuncAttributeMaxDynamicSharedMemorySize, SMEM_BYTES);

    __half *ah, *bh;
    cudaGetSymbolAddress((void**)&ah, g_ah);
    cudaGetSymbolAddress((void**)&bh, g_bh);

    init_kernel<<<(B_ * S_ + 255) / 256, 256>>>(out);
    cvt_h_kernel<<<(size_t)M_ * K_ / 2048, 256>>>(enc, ah);
    cvt_h_kernel<<<(size_t)D_ * K_ / 2048, 256>>>(We, bh);
    dec_proj_kernel<<<(B_ * (D_ / 4) * 32 + 255) / 256, 256>>>(hidden, Wd);
    score_mma_kernel<<<dim3(NT, MT), 256, SMEM_BYTES>>>(v);
    softmax_kernel<<<B_, 256>>>(wout);
    context_kernel<<<dim3(E_ / 512, B_, CSPLIT), 256>>>(wout, out);
}